// round 2
// baseline (speedup 1.0000x reference)
#include <cuda_runtime.h>
#include <math.h>
#include <stdint.h>

#define B_ 2
#define S_ 2048
#define D_ 1024
#define H_ 16
#define KH_ 4
#define HD_ 64
#define E_ 8
#define FF_ 2048
#define NTOK (B_*S_)            // 4096
#define NSLOT (NTOK*2)          // 8192 (token, expert) pairs
#define NEG_BIG -3.0e38f

// ---------------- scratch (device globals: allocation-free) ----------------
__device__ float g_xn  [NTOK*D_];
__device__ float g_q   [NTOK*H_*HD_];
__device__ float g_k   [NTOK*KH_*HD_];
__device__ float g_v   [NTOK*KH_*HD_];
__device__ float g_gate[NTOK*H_*HD_];
__device__ float g_attn[NTOK*H_*HD_];
__device__ float g_x1  [NTOK*D_];
__device__ float g_xn2 [NTOK*D_];
__device__ float g_h   [NSLOT*FF_];   // h1 then h (in place)
__device__ float g_tmp [NSLOT*D_];    // per-slot expert outputs (scaled)
__device__ int   g_topi[NTOK*2];
__device__ float g_topv[NTOK*2];
__device__ int   g_permTok[NSLOT];
__device__ float g_permW  [NSLOT];
__device__ int   g_tokSlot[NTOK*2];
__device__ int   g_counts[E_];
__device__ int   g_off   [E_+1];
__device__ int   g_cursor[E_];
__device__ float g_probsum[E_];

// ---------------- rmsnorm over D=1024 (1 block / token, 256 thr) ----------
__global__ void rmsnorm_kernel(const float* __restrict__ x,
                               const float* __restrict__ w,
                               float* __restrict__ out, float eps) {
    int t = blockIdx.x;
    const float4* xr = (const float4*)(x + (size_t)t * D_);
    float4 v = xr[threadIdx.x];
    float ss = v.x*v.x + v.y*v.y + v.z*v.z + v.w*v.w;
    __shared__ float sm[8];
    for (int o = 16; o > 0; o >>= 1) ss += __shfl_xor_sync(0xffffffffu, ss, o);
    if ((threadIdx.x & 31) == 0) sm[threadIdx.x >> 5] = ss;
    __syncthreads();
    if (threadIdx.x < 8) {
        float s2 = sm[threadIdx.x];
        for (int o = 4; o > 0; o >>= 1) s2 += __shfl_xor_sync(0xffu, s2, o);
        if (threadIdx.x == 0) sm[0] = s2;
    }
    __syncthreads();
    float sc = rsqrtf(sm[0] * (1.0f / D_) + eps);
    const float4* wr = (const float4*)w;
    float4 wv = wr[threadIdx.x];
    float4 o4 = make_float4(v.x*sc*wv.x, v.y*sc*wv.y, v.z*sc*wv.z, v.w*sc*wv.w);
    ((float4*)(out + (size_t)t * D_))[threadIdx.x] = o4;
}

// ---------------- generic SGEMM 128x128x8, 256 thr, 8x8/thread ------------
// EPI: 0 = C=acc ; 1 = C=X+acc (residual) ; 2 = C=silu(Cprev)*acc (in-place) ;
//      3 = C=X[row]*acc (per-row scale)
// rowmap: A-row gather (nullptr = identity). range: {start,end} device ptr.
template<int EPI>
__global__ void sgemm_kernel(const float* __restrict__ A, const float* __restrict__ B,
                             float* __restrict__ C, const float* __restrict__ X,
                             int M, int N, int K,
                             const int* __restrict__ rowmap,
                             const int* __restrict__ range) {
    __shared__ float As[8][128];
    __shared__ float Bs[8][128];
    int tid = threadIdx.x;
    int start = 0, end = M;
    if (range) { start = range[0]; end = range[1]; }
    int rowbase = start + blockIdx.y * 128;
    if (rowbase >= end) return;
    int nbase = blockIdx.x * 128;
    int tx = tid & 15, ty = tid >> 4;
    int arow_l = tid >> 1;
    int acol_l = (tid & 1) * 4;
    int brow_l = tid >> 5;
    int bcol_l = (tid & 31) * 4;
    int grow_l = rowbase + arow_l;
    bool avalid = grow_l < end;
    int arow_g = 0;
    if (avalid) arow_g = rowmap ? rowmap[grow_l] : grow_l;
    const float* Aptr = A + (size_t)arow_g * K + acol_l;
    const float* Bptr = B + (size_t)brow_l * N + nbase + bcol_l;

    float acc[8][8];
#pragma unroll
    for (int i = 0; i < 8; i++)
#pragma unroll
        for (int j = 0; j < 8; j++) acc[i][j] = 0.f;

    for (int k0 = 0; k0 < K; k0 += 8) {
        float4 a4 = avalid ? *(const float4*)(Aptr + k0) : make_float4(0, 0, 0, 0);
        As[acol_l + 0][arow_l] = a4.x;
        As[acol_l + 1][arow_l] = a4.y;
        As[acol_l + 2][arow_l] = a4.z;
        As[acol_l + 3][arow_l] = a4.w;
        float4 b4 = *(const float4*)(Bptr + (size_t)k0 * N);
        *(float4*)&Bs[brow_l][bcol_l] = b4;
        __syncthreads();
#pragma unroll
        for (int kk = 0; kk < 8; kk++) {
            float ar[8], br[8];
#pragma unroll
            for (int i = 0; i < 8; i++) ar[i] = As[kk][ty * 8 + i];
#pragma unroll
            for (int j = 0; j < 8; j++) br[j] = Bs[kk][tx * 8 + j];
#pragma unroll
            for (int i = 0; i < 8; i++)
#pragma unroll
                for (int j = 0; j < 8; j++) acc[i][j] += ar[i] * br[j];
        }
        __syncthreads();
    }
#pragma unroll
    for (int i = 0; i < 8; i++) {
        int grow = rowbase + ty * 8 + i;
        if (grow >= end) continue;
        size_t rowoff = (size_t)grow * N;
#pragma unroll
        for (int j = 0; j < 8; j++) {
            int col = nbase + tx * 8 + j;
            size_t idx = rowoff + col;
            float v = acc[i][j];
            if (EPI == 0) {
                C[idx] = v;
            } else if (EPI == 1) {
                C[idx] = X[idx] + v;
            } else if (EPI == 2) {
                float h1 = C[idx];
                C[idx] = h1 / (1.f + __expf(-h1)) * v;
            } else {
                C[idx] = X[grow] * v;
            }
        }
    }
}

// -------- per-head rmsnorm (eps 1e-5) + RoPE, one warp per (token, head) ---
__global__ void qkrope_kernel(float* buf, const float* __restrict__ w,
                              int nheads, int ntok) {
    int wid = (blockIdx.x * blockDim.x + threadIdx.x) >> 5;
    int lane = threadIdx.x & 31;
    if (wid >= ntok * nheads) return;
    int t = wid / nheads, h = wid - t * nheads;
    int pos = t & (S_ - 1);
    size_t base = (size_t)t * nheads * HD_ + h * HD_;
    float v0 = buf[base + 2 * lane];
    float v1 = buf[base + 2 * lane + 1];
    float ss = v0 * v0 + v1 * v1;
    for (int o = 16; o > 0; o >>= 1) ss += __shfl_xor_sync(0xffffffffu, ss, o);
    float sc = rsqrtf(ss * (1.0f / HD_) + 1e-5f);
    float a  = v0 * sc * w[2 * lane];
    float b2 = v1 * sc * w[2 * lane + 1];
    // inv = 10000^(-2*lane/64)
    float inv = expf(-(float)lane * (2.0f / HD_) * 9.210340371976184f);
    float ang = (float)pos * inv;
    float cs = cosf(ang), sn = sinf(ang);
    buf[base + 2 * lane]     = a * cs - b2 * sn;
    buf[base + 2 * lane + 1] = a * sn + b2 * cs;
}

// ---------------- flash attention, causal, BQ=64 BK=32, 256 thr ------------
__global__ void attn_kernel(const float* __restrict__ Q, const float* __restrict__ Kb,
                            const float* __restrict__ Vb, float* __restrict__ O) {
    __shared__ float Qs[64][68];
    __shared__ float Ks[32][68];
    __shared__ float Vs[32][68];
    __shared__ float Ps[64][36];
    int qt = blockIdx.x, h = blockIdx.y, b = blockIdx.z;
    int kh = h >> 2;
    int tid = threadIdx.x;
    int r = tid >> 2, c = tid & 3;   // row 0..63, quad 0..3

    {   // load + scale Q tile
        int row = tid >> 2;
        int col0 = (tid & 3) * 16;
        size_t base = ((size_t)(b * S_ + qt * 64 + row)) * (H_ * HD_) + h * HD_ + col0;
#pragma unroll
        for (int i = 0; i < 4; i++) {
            float4 v = *(const float4*)(Q + base + i * 4);
            Qs[row][col0 + i * 4 + 0] = v.x * 0.125f;
            Qs[row][col0 + i * 4 + 1] = v.y * 0.125f;
            Qs[row][col0 + i * 4 + 2] = v.z * 0.125f;
            Qs[row][col0 + i * 4 + 3] = v.w * 0.125f;
        }
    }

    float o[16];
#pragma unroll
    for (int i = 0; i < 16; i++) o[i] = 0.f;
    float m = NEG_BIG, l = 0.f;
    int qg = qt * 64 + r;
    int nkt = 2 * (qt + 1);

    for (int kt = 0; kt < nkt; kt++) {
        __syncthreads();  // previous-iter smem reads done (also covers Qs fill)
        {   // load K,V tile: 32 rows x 64
            int row = tid >> 3;
            int col0 = (tid & 7) * 8;
            size_t base = ((size_t)(b * S_ + kt * 32 + row)) * (KH_ * HD_) + kh * HD_ + col0;
            float4 k1 = *(const float4*)(Kb + base);
            float4 k2 = *(const float4*)(Kb + base + 4);
            *(float4*)&Ks[row][col0]     = k1;
            *(float4*)&Ks[row][col0 + 4] = k2;
            float4 v1 = *(const float4*)(Vb + base);
            float4 v2 = *(const float4*)(Vb + base + 4);
            *(float4*)&Vs[row][col0]     = v1;
            *(float4*)&Vs[row][col0 + 4] = v2;
        }
        __syncthreads();

        float p[8];
        float tmax = NEG_BIG;
#pragma unroll
        for (int jj = 0; jj < 8; jj++) {
            int j = c * 8 + jj;
            float s = 0.f;
#pragma unroll
            for (int d = 0; d < 64; d++) s += Qs[r][d] * Ks[j][d];
            int kg = kt * 32 + j;
            if (kg > qg) s = NEG_BIG;
            p[jj] = s;
            tmax = fmaxf(tmax, s);
        }
        tmax = fmaxf(tmax, __shfl_xor_sync(0xffffffffu, tmax, 1));
        tmax = fmaxf(tmax, __shfl_xor_sync(0xffffffffu, tmax, 2));
        float m_new = fmaxf(m, tmax);
        float alpha = __expf(m - m_new);  // underflows to 0 on first tile
        float ls = 0.f;
#pragma unroll
        for (int jj = 0; jj < 8; jj++) {
            float e = __expf(p[jj] - m_new);
            p[jj] = e;
            ls += e;
        }
        ls += __shfl_xor_sync(0xffffffffu, ls, 1);
        ls += __shfl_xor_sync(0xffffffffu, ls, 2);
        l = l * alpha + ls;
        m = m_new;
#pragma unroll
        for (int dd = 0; dd < 16; dd++) o[dd] *= alpha;
#pragma unroll
        for (int jj = 0; jj < 8; jj++) Ps[r][c * 8 + jj] = p[jj];
        __syncthreads();
#pragma unroll
        for (int j2 = 0; j2 < 32; j2++) {
            float pv = Ps[r][j2];
#pragma unroll
            for (int dd = 0; dd < 16; dd++) o[dd] += pv * Vs[j2][c * 16 + dd];
        }
    }
    float inv_l = 1.f / l;
    size_t obase = ((size_t)(b * S_ + qg)) * (H_ * HD_) + h * HD_ + c * 16;
#pragma unroll
    for (int dd = 0; dd < 16; dd++) O[obase + dd] = o[dd] * inv_l;
}

// ---------------- elementwise: gate = attn * sigmoid(gate) -----------------
__global__ void gatemul_kernel() {
    size_t i = (size_t)blockIdx.x * 256 + threadIdx.x;
    float g = g_gate[i];
    g_gate[i] = g_attn[i] * (1.f / (1.f + expf(-g)));
}

// ---------------- router: logits, softmax, top2, aux partials --------------
__global__ void router_kernel(const float* __restrict__ rw) {
    int t = blockIdx.x;
    const float* x = g_xn2 + (size_t)t * D_;
    float le[8] = {0, 0, 0, 0, 0, 0, 0, 0};
    for (int d = threadIdx.x; d < D_; d += 256) {
        float xv = x[d];
        const float4* r4 = (const float4*)(rw + (size_t)d * 8);
        float4 aa = r4[0], bb = r4[1];
        le[0] += xv * aa.x; le[1] += xv * aa.y; le[2] += xv * aa.z; le[3] += xv * aa.w;
        le[4] += xv * bb.x; le[5] += xv * bb.y; le[6] += xv * bb.z; le[7] += xv * bb.w;
    }
#pragma unroll
    for (int e = 0; e < 8; e++)
        for (int o = 16; o > 0; o >>= 1)
            le[e] += __shfl_xor_sync(0xffffffffu, le[e], o);
    __shared__ float sm[8][8];
    if ((threadIdx.x & 31) == 0)
#pragma unroll
        for (int e = 0; e < 8; e++) sm[threadIdx.x >> 5][e] = le[e];
    __syncthreads();
    if (threadIdx.x == 0) {
        float lg[8];
#pragma unroll
        for (int e = 0; e < 8; e++) {
            float s = 0.f;
            for (int w = 0; w < 8; w++) s += sm[w][e];
            lg[e] = s;
        }
        float mx = lg[0];
        for (int e = 1; e < 8; e++) mx = fmaxf(mx, lg[e]);
        float p[8], s = 0.f;
        for (int e = 0; e < 8; e++) { p[e] = expf(lg[e] - mx); s += p[e]; }
        float invs = 1.f / s;
        for (int e = 0; e < 8; e++) {
            p[e] *= invs;
            atomicAdd(&g_probsum[e], p[e]);
        }
        int i0 = 0;
        for (int e = 1; e < 8; e++) if (p[e] > p[i0]) i0 = e;
        int i1 = (i0 == 0) ? 1 : 0;
        for (int e = 0; e < 8; e++) if (e != i0 && p[e] > p[i1]) i1 = e;
        float tv0 = p[i0], tv1 = p[i1], s2 = tv0 + tv1;
        g_topi[t * 2] = i0; g_topi[t * 2 + 1] = i1;
        g_topv[t * 2] = tv0 / s2; g_topv[t * 2 + 1] = tv1 / s2;
        atomicAdd(&g_counts[i0], 1);
        atomicAdd(&g_counts[i1], 1);
    }
}

__global__ void zero_kernel() {
    int t = threadIdx.x;
    if (t < E_) { g_counts[t] = 0; g_cursor[t] = 0; g_probsum[t] = 0.f; }
}

__global__ void offsets_aux_kernel(float* __restrict__ aux_out) {
    if (threadIdx.x == 0) {
        int o = 0;
        for (int e = 0; e < E_; e++) { g_off[e] = o; o += g_counts[e]; }
        g_off[E_] = o;
        float aux = 0.f;
        for (int e = 0; e < E_; e++)
            aux += ((float)g_counts[e] / (NTOK * 2.0f)) * (g_probsum[e] / (float)NTOK);
        aux_out[0] = 0.01f * (float)E_ * aux;
    }
}

__global__ void scatter_kernel() {
    int t = blockIdx.x * 256 + threadIdx.x;
    if (t >= NTOK) return;
#pragma unroll
    for (int k2 = 0; k2 < 2; k2++) {
        int e = g_topi[t * 2 + k2];
        int pos = g_off[e] + atomicAdd(&g_cursor[e], 1);
        g_permTok[pos] = t;
        g_permW[pos] = g_topv[t * 2 + k2];
        g_tokSlot[t * 2 + k2] = pos;
    }
}

__global__ void finaladd_kernel(float* __restrict__ out) {
    size_t i = (size_t)blockIdx.x * 256 + threadIdx.x;
    int t = (int)(i >> 10);
    int d = (int)(i & 1023);
    int s0 = g_tokSlot[t * 2], s1 = g_tokSlot[t * 2 + 1];
    out[i] = g_x1[i] + g_tmp[(size_t)s0 * D_ + d] + g_tmp[(size_t)s1 * D_ + d];
}

// ---------------- host launcher -------------------------------------------
extern "C" void kernel_launch(void* const* d_in, const int* in_sizes, int n_in,
                              void* d_out, int out_size) {
    const float* x        = (const float*)d_in[0];
    const float* attn_nw  = (const float*)d_in[1];
    const float* ffn_nw   = (const float*)d_in[2];
    const float* q_nw     = (const float*)d_in[3];
    const float* k_nw     = (const float*)d_in[4];
    const float* wq       = (const float*)d_in[5];
    const float* wk       = (const float*)d_in[6];
    const float* wv       = (const float*)d_in[7];
    const float* wo       = (const float*)d_in[8];
    const float* wg       = (const float*)d_in[9];
    const float* router_w = (const float*)d_in[10];
    const float* w1       = (const float*)d_in[11];
    const float* w3       = (const float*)d_in[12];
    const float* w2       = (const float*)d_in[13];
    float* out = (float*)d_out;

    float *p_xn, *p_q, *p_k, *p_v, *p_gate, *p_attn, *p_x1, *p_xn2, *p_h, *p_tmp, *p_permW;
    int *p_permTok, *p_off;
    cudaGetSymbolAddress((void**)&p_xn, g_xn);
    cudaGetSymbolAddress((void**)&p_q, g_q);
    cudaGetSymbolAddress((void**)&p_k, g_k);
    cudaGetSymbolAddress((void**)&p_v, g_v);
    cudaGetSymbolAddress((void**)&p_gate, g_gate);
    cudaGetSymbolAddress((void**)&p_attn, g_attn);
    cudaGetSymbolAddress((void**)&p_x1, g_x1);
    cudaGetSymbolAddress((void**)&p_xn2, g_xn2);
    cudaGetSymbolAddress((void**)&p_h, g_h);
    cudaGetSymbolAddress((void**)&p_tmp, g_tmp);
    cudaGetSymbolAddress((void**)&p_permW, g_permW);
    cudaGetSymbolAddress((void**)&p_permTok, g_permTok);
    cudaGetSymbolAddress((void**)&p_off, g_off);

    // 1. attn rmsnorm
    rmsnorm_kernel<<<NTOK, 256>>>(x, attn_nw, p_xn, 1e-6f);
    // 2. QKV + gate projections
    sgemm_kernel<0><<<dim3(8, 32), 256>>>(p_xn, wq, p_q, nullptr, NTOK, 1024, 1024, nullptr, nullptr);
    sgemm_kernel<0><<<dim3(2, 32), 256>>>(p_xn, wk, p_k, nullptr, NTOK, 256, 1024, nullptr, nullptr);
    sgemm_kernel<0><<<dim3(2, 32), 256>>>(p_xn, wv, p_v, nullptr, NTOK, 256, 1024, nullptr, nullptr);
    sgemm_kernel<0><<<dim3(8, 32), 256>>>(p_xn, wg, p_gate, nullptr, NTOK, 1024, 1024, nullptr, nullptr);
    // 3. q/k norm + rope
    qkrope_kernel<<<(NTOK * H_ * 32) / 256, 256>>>(p_q, q_nw, H_, NTOK);
    qkrope_kernel<<<(NTOK * KH_ * 32) / 256, 256>>>(p_k, k_nw, KH_, NTOK);
    // 4. attention
    attn_kernel<<<dim3(S_ / 64, H_, B_), 256>>>(p_q, p_k, p_v, p_attn);
    // 5. gate
    gatemul_kernel<<<(NTOK * 1024) / 256, 256>>>();
    // 6. output proj + residual
    sgemm_kernel<1><<<dim3(8, 32), 256>>>(p_gate, wo, p_x1, x, NTOK, 1024, 1024, nullptr, nullptr);
    // 7. ffn rmsnorm
    rmsnorm_kernel<<<NTOK, 256>>>(p_x1, ffn_nw, p_xn2, 1e-6f);
    // 8. router + permutation + aux
    zero_kernel<<<1, 32>>>();
    router_kernel<<<NTOK, 256>>>(router_w);
    offsets_aux_kernel<<<1, 32>>>(out + (size_t)NTOK * D_);
    scatter_kernel<<<NTOK / 256, 256>>>();
    // 9. MoE grouped GEMMs (per-expert launches, device-side row ranges)
    for (int e = 0; e < E_; e++)
        sgemm_kernel<0><<<dim3(FF_ / 128, NSLOT / 128), 256>>>(
            p_xn2, w1 + (size_t)e * D_ * FF_, p_h, nullptr, NSLOT, FF_, D_, p_permTok, p_off + e);
    for (int e = 0; e < E_; e++)
        sgemm_kernel<2><<<dim3(FF_ / 128, NSLOT / 128), 256>>>(
            p_xn2, w3 + (size_t)e * D_ * FF_, p_h, nullptr, NSLOT, FF_, D_, p_permTok, p_off + e);
    for (int e = 0; e < E_; e++)
        sgemm_kernel<3><<<dim3(D_ / 128, NSLOT / 128), 256>>>(
            p_h, w2 + (size_t)e * FF_ * D_, p_tmp, p_permW, NSLOT, D_, FF_, nullptr, p_off + e);
    // 10. final residual add
    finaladd_kernel<<<(NTOK * 1024) / 256, 256>>>(out);
}

// round 3
// speedup vs baseline: 5.5931x; 5.5931x over previous
#include <cuda_runtime.h>
#include <math.h>
#include <stdint.h>

#define B_ 2
#define S_ 2048
#define D_ 1024
#define H_ 16
#define KH_ 4
#define HD_ 64
#define E_ 8
#define FF_ 2048
#define NTOK (B_*S_)
#define NSLOT (NTOK*2)
#define NEG_BIG -3.0e38f

#define BM 128
#define BN 128
#define LDA 36
#define LDB 136
#define SMEM_GEMM   ((BM*LDA + 32*LDB)*4)
#define SMEM_GEMM_S ((BM*LDA + 32*LDB)*8)
#define SMEM_ATTN   ((64*132 + 64*68 + 64*68 + 128*68)*4)

__device__ float g_xn  [NTOK*D_];
__device__ float g_q   [NTOK*H_*HD_];
__device__ float g_k   [NTOK*KH_*HD_];
__device__ float g_v   [NTOK*KH_*HD_];
__device__ float g_gate[NTOK*H_*HD_];
__device__ float g_attn[NTOK*H_*HD_];
__device__ float g_x1  [NTOK*D_];
__device__ float g_xn2 [NTOK*D_];
__device__ float g_h   [(size_t)NSLOT*FF_];
__device__ float g_h3  [(size_t)NSLOT*FF_];
__device__ float g_tmp [(size_t)NSLOT*D_];
__device__ int   g_topi[NTOK*2];
__device__ float g_topv[NTOK*2];
__device__ int   g_permTok[NSLOT];
__device__ float g_permW  [NSLOT];
__device__ int   g_tokSlot[NTOK*2];
__device__ int   g_counts[E_];
__device__ int   g_off   [E_+1];
__device__ int   g_cursor[E_];
__device__ float g_probsum[E_];

__device__ __forceinline__ unsigned f2tf(float v) {
    unsigned r; asm("cvt.rna.tf32.f32 %0, %1;" : "=r"(r) : "f"(v)); return r;
}
__device__ __forceinline__ void mma_tf32(float* d, const unsigned* a, unsigned b0, unsigned b1) {
    asm volatile("mma.sync.aligned.m16n8k8.row.col.f32.tf32.tf32.f32 "
        "{%0,%1,%2,%3}, {%4,%5,%6,%7}, {%8,%9}, {%0,%1,%2,%3};"
        : "+f"(d[0]), "+f"(d[1]), "+f"(d[2]), "+f"(d[3])
        : "r"(a[0]), "r"(a[1]), "r"(a[2]), "r"(a[3]), "r"(b0), "r"(b1));
}

// ---- tf32 MMA GEMM core 128x128x32, 256 thr. EPI: 0 plain, 1 +X, 3 X[row]*acc
template<int EPI, bool SPLIT>
__device__ __forceinline__ void gemm_core(
    const float* __restrict__ A, const float* __restrict__ B,
    float* __restrict__ C, const float* __restrict__ X,
    int N, int K, int ldc, int rowstart, int rowend,
    const int* __restrict__ rowmap, int bx, int by)
{
    extern __shared__ float sm[];
    float* Ah = sm;
    float* Bh = Ah + BM*LDA;
    float* Al = Bh + 32*LDB;
    float* Bl = Al + BM*LDA;

    int tid = threadIdx.x;
    int rowbase = rowstart + by*BM;
    if (rowbase >= rowend) return;
    int nbase = bx*BN;

    int k4 = tid & 7;
    int n4 = tid & 31;
    const float* aP[4]; bool av[4];
#pragma unroll
    for (int i = 0; i < 4; i++) {
        int grow = rowbase + (tid >> 3) + 32*i;
        av[i] = grow < rowend;
        int ar = av[i] ? (rowmap ? rowmap[grow] : grow)
                       : (rowmap ? rowmap[rowstart] : rowstart);
        aP[i] = A + (size_t)ar*K + k4*4;
    }
    const float* bP = B + (size_t)(tid>>5)*N + nbase + n4*4;

    int lane = tid & 31, gp = lane >> 2, t4 = lane & 3;
    int w = tid >> 5, mb = (w & 3)*32, nb = (w >> 2)*64;

    float acc[2][8][4];
#pragma unroll
    for (int a = 0; a < 2; a++)
#pragma unroll
        for (int b = 0; b < 8; b++)
#pragma unroll
            for (int c = 0; c < 4; c++) acc[a][b][c] = 0.f;

    float4 va[4], vb[4];
#pragma unroll
    for (int i = 0; i < 4; i++) {
        va[i] = av[i] ? *(const float4*)(aP[i]) : make_float4(0,0,0,0);
        vb[i] = *(const float4*)(bP + (size_t)(8*i)*N);
    }

    int nkt = K >> 5;
    for (int kt = 0; kt < nkt; kt++) {
#pragma unroll
        for (int i = 0; i < 4; i++) {
            int m = (tid >> 3) + 32*i;
            float vv[4] = {va[i].x, va[i].y, va[i].z, va[i].w};
            float4 hi, lo;
            float* hp = &hi.x; float* lp = &lo.x;
#pragma unroll
            for (int j = 0; j < 4; j++) {
                unsigned h = f2tf(vv[j]);
                hp[j] = __uint_as_float(h);
                if (SPLIT) lp[j] = __uint_as_float(f2tf(vv[j] - __uint_as_float(h)));
            }
            *(float4*)(Ah + m*LDA + k4*4) = hi;
            if (SPLIT) *(float4*)(Al + m*LDA + k4*4) = lo;

            int kr = (tid >> 5) + 8*i;
            float bv[4] = {vb[i].x, vb[i].y, vb[i].z, vb[i].w};
#pragma unroll
            for (int j = 0; j < 4; j++) {
                unsigned h = f2tf(bv[j]);
                hp[j] = __uint_as_float(h);
                if (SPLIT) lp[j] = __uint_as_float(f2tf(bv[j] - __uint_as_float(h)));
            }
            *(float4*)(Bh + kr*LDB + n4*4) = hi;
            if (SPLIT) *(float4*)(Bl + kr*LDB + n4*4) = lo;
        }
        __syncthreads();
        if (kt + 1 < nkt) {
#pragma unroll
            for (int i = 0; i < 4; i++) {
                va[i] = av[i] ? *(const float4*)(aP[i] + (kt+1)*32) : make_float4(0,0,0,0);
                vb[i] = *(const float4*)(bP + (size_t)((kt+1)*32 + 8*i)*N);
            }
        }
#pragma unroll
        for (int ks = 0; ks < 4; ks++) {
            int kf = ks*8 + t4;
            unsigned a[2][4], al[2][4];
#pragma unroll
            for (int mt = 0; mt < 2; mt++) {
                int r = mb + mt*16 + gp;
                a[mt][0] = __float_as_uint(Ah[r*LDA + kf]);
                a[mt][1] = __float_as_uint(Ah[(r+8)*LDA + kf]);
                a[mt][2] = __float_as_uint(Ah[r*LDA + kf + 4]);
                a[mt][3] = __float_as_uint(Ah[(r+8)*LDA + kf + 4]);
                if (SPLIT) {
                    al[mt][0] = __float_as_uint(Al[r*LDA + kf]);
                    al[mt][1] = __float_as_uint(Al[(r+8)*LDA + kf]);
                    al[mt][2] = __float_as_uint(Al[r*LDA + kf + 4]);
                    al[mt][3] = __float_as_uint(Al[(r+8)*LDA + kf + 4]);
                }
            }
#pragma unroll
            for (int nt = 0; nt < 8; nt++) {
                int c = nb + nt*8 + gp;
                unsigned b0 = __float_as_uint(Bh[kf*LDB + c]);
                unsigned b1 = __float_as_uint(Bh[(kf+4)*LDB + c]);
#pragma unroll
                for (int mt = 0; mt < 2; mt++) mma_tf32(acc[mt][nt], a[mt], b0, b1);
                if (SPLIT) {
                    unsigned c0 = __float_as_uint(Bl[kf*LDB + c]);
                    unsigned c1 = __float_as_uint(Bl[(kf+4)*LDB + c]);
#pragma unroll
                    for (int mt = 0; mt < 2; mt++) {
                        mma_tf32(acc[mt][nt], a[mt], c0, c1);
                        mma_tf32(acc[mt][nt], al[mt], b0, b1);
                    }
                }
            }
        }
        __syncthreads();
    }
#pragma unroll
    for (int mt = 0; mt < 2; mt++) {
        int r0 = rowbase + mb + mt*16 + gp;
        int r1 = r0 + 8;
        float s0 = 0.f, s1 = 0.f;
        if (EPI == 3) {
            s0 = (r0 < rowend) ? X[r0] : 0.f;
            s1 = (r1 < rowend) ? X[r1] : 0.f;
        }
#pragma unroll
        for (int nt = 0; nt < 8; nt++) {
            int col = nbase + nb + nt*8 + t4*2;
            if (r0 < rowend) {
                float2 v = make_float2(acc[mt][nt][0], acc[mt][nt][1]);
                if (EPI == 1) { float2 xr = *(const float2*)(X + (size_t)r0*ldc + col); v.x += xr.x; v.y += xr.y; }
                if (EPI == 3) { v.x *= s0; v.y *= s0; }
                *(float2*)(C + (size_t)r0*ldc + col) = v;
            }
            if (r1 < rowend) {
                float2 v = make_float2(acc[mt][nt][2], acc[mt][nt][3]);
                if (EPI == 1) { float2 xr = *(const float2*)(X + (size_t)r1*ldc + col); v.x += xr.x; v.y += xr.y; }
                if (EPI == 3) { v.x *= s1; v.y *= s1; }
                *(float2*)(C + (size_t)r1*ldc + col) = v;
            }
        }
    }
}

template<int EPI, bool SPLIT>
__global__ void __launch_bounds__(256) gemm_plain(
    const float* __restrict__ A, const float* __restrict__ B,
    float* __restrict__ C, const float* __restrict__ X, int N, int K, int M)
{
    gemm_core<EPI,SPLIT>(A, B, C, X, N, K, N, 0, M, nullptr, blockIdx.x, blockIdx.y);
}

__global__ void __launch_bounds__(256) moe13_gemm(
    const float* __restrict__ w1, const float* __restrict__ w3)
{
    int z = blockIdx.z, e = z >> 1;
    const float* B = ((z & 1) ? w3 : w1) + (size_t)e*D_*FF_;
    float* C = (z & 1) ? g_h3 : g_h;
    gemm_core<0,false>(g_xn2, B, C, nullptr, FF_, D_, FF_,
                       g_off[e], g_off[e+1], g_permTok, blockIdx.x, blockIdx.y);
}

__global__ void __launch_bounds__(256) moe2_gemm(const float* __restrict__ w2)
{
    int e = blockIdx.z;
    gemm_core<3,false>(g_h, w2 + (size_t)e*FF_*D_, g_tmp, g_permW, D_, FF_, D_,
                       g_off[e], g_off[e+1], nullptr, blockIdx.x, blockIdx.y);
}

// ---------------- rmsnorm ----------------
__global__ void rmsnorm_kernel(const float* __restrict__ x, const float* __restrict__ w,
                               float* __restrict__ out, float eps) {
    int t = blockIdx.x;
    const float4* xr = (const float4*)(x + (size_t)t * D_);
    float4 v = xr[threadIdx.x];
    float ss = v.x*v.x + v.y*v.y + v.z*v.z + v.w*v.w;
    __shared__ float smr[8];
    for (int o = 16; o > 0; o >>= 1) ss += __shfl_xor_sync(0xffffffffu, ss, o);
    if ((threadIdx.x & 31) == 0) smr[threadIdx.x >> 5] = ss;
    __syncthreads();
    if (threadIdx.x < 8) {
        float s2 = smr[threadIdx.x];
        for (int o = 4; o > 0; o >>= 1) s2 += __shfl_xor_sync(0xffu, s2, o);
        if (threadIdx.x == 0) smr[0] = s2;
    }
    __syncthreads();
    float sc = rsqrtf(smr[0] * (1.0f / D_) + eps);
    float4 wv = ((const float4*)w)[threadIdx.x];
    ((float4*)(out + (size_t)t * D_))[threadIdx.x] =
        make_float4(v.x*sc*wv.x, v.y*sc*wv.y, v.z*sc*wv.z, v.w*sc*wv.w);
}

// ---------------- q/k rmsnorm + rope ----------------
__global__ void qkrope_kernel(float* buf, const float* __restrict__ w, int nheads) {
    int wid = (blockIdx.x * blockDim.x + threadIdx.x) >> 5;
    int lane = threadIdx.x & 31;
    int t = wid / nheads, h = wid - t * nheads;
    int pos = t & (S_ - 1);
    size_t base = (size_t)t * nheads * HD_ + h * HD_;
    float v0 = buf[base + 2*lane], v1 = buf[base + 2*lane + 1];
    float ss = v0*v0 + v1*v1;
    for (int o = 16; o > 0; o >>= 1) ss += __shfl_xor_sync(0xffffffffu, ss, o);
    float sc = rsqrtf(ss * (1.0f / HD_) + 1e-5f);
    float a  = v0 * sc * w[2*lane];
    float b2 = v1 * sc * w[2*lane + 1];
    float inv = expf(-(float)lane * (2.0f / HD_) * 9.210340371976184f);
    float ang = (float)pos * inv;
    float cs = cosf(ang), sn = sinf(ang);
    buf[base + 2*lane]     = a*cs - b2*sn;
    buf[base + 2*lane + 1] = a*sn + b2*cs;
}

// ---------------- flash attention v2: BQ=128 BK=64, 8x4/thread --------------
__global__ void __launch_bounds__(256) attn_v2(
    const float* __restrict__ Q, const float* __restrict__ Kb,
    const float* __restrict__ Vb, float* __restrict__ O)
{
    extern __shared__ float smA[];
    float* QsT = smA;                // [64][132] (d,q)
    float* KsT = QsT + 64*132;       // [64][68]  (d,k)
    float* Vs  = KsT + 64*68;        // [64][68]  (k,d)
    float* Ps  = Vs  + 64*68;        // [128][68] (q,k)
    int qt = blockIdx.x, h = blockIdx.y, b = blockIdx.z;
    int kh = h >> 2;
    int tid = threadIdx.x;
    int ty = tid >> 4, tx = tid & 15;

#pragma unroll
    for (int i = 0; i < 8; i++) {
        int id = tid + i*256;
        int q = id >> 4, d4 = id & 15;
        float4 v = *(const float4*)(Q + ((size_t)(b*S_ + qt*128 + q))*(H_*HD_) + h*HD_ + d4*4);
        QsT[(d4*4+0)*132 + q] = v.x * 0.125f;
        QsT[(d4*4+1)*132 + q] = v.y * 0.125f;
        QsT[(d4*4+2)*132 + q] = v.z * 0.125f;
        QsT[(d4*4+3)*132 + q] = v.w * 0.125f;
    }

    float m[8], l[8], o[8][4];
#pragma unroll
    for (int i = 0; i < 8; i++) {
        m[i] = NEG_BIG; l[i] = 0.f;
#pragma unroll
        for (int j = 0; j < 4; j++) o[i][j] = 0.f;
    }
    int nkt = 2*(qt+1);

    for (int kt = 0; kt < nkt; kt++) {
        __syncthreads();
#pragma unroll
        for (int i = 0; i < 4; i++) {
            int id = tid + i*256;
            int k = id >> 4, d4 = id & 15;
            size_t gb = ((size_t)(b*S_ + kt*64 + k))*(KH_*HD_) + kh*HD_ + d4*4;
            float4 kv = *(const float4*)(Kb + gb);
            KsT[(d4*4+0)*68 + k] = kv.x;
            KsT[(d4*4+1)*68 + k] = kv.y;
            KsT[(d4*4+2)*68 + k] = kv.z;
            KsT[(d4*4+3)*68 + k] = kv.w;
            *(float4*)&Vs[k*68 + d4*4] = *(const float4*)(Vb + gb);
        }
        __syncthreads();

        float s[8][4];
#pragma unroll
        for (int i = 0; i < 8; i++)
#pragma unroll
            for (int j = 0; j < 4; j++) s[i][j] = 0.f;
#pragma unroll 4
        for (int d = 0; d < 64; d++) {
            float4 q0 = *(float4*)&QsT[d*132 + ty*8];
            float4 q1 = *(float4*)&QsT[d*132 + ty*8 + 4];
            float4 kk = *(float4*)&KsT[d*68 + tx*4];
            float qa[8] = {q0.x,q0.y,q0.z,q0.w,q1.x,q1.y,q1.z,q1.w};
            float kb2[4] = {kk.x,kk.y,kk.z,kk.w};
#pragma unroll
            for (int i = 0; i < 8; i++)
#pragma unroll
                for (int j = 0; j < 4; j++) s[i][j] += qa[i]*kb2[j];
        }
        int qg0 = qt*128 + ty*8;
        int kg0 = kt*64 + tx*4;
#pragma unroll
        for (int i = 0; i < 8; i++)
#pragma unroll
            for (int j = 0; j < 4; j++)
                if (kg0 + j > qg0 + i) s[i][j] = NEG_BIG;

#pragma unroll
        for (int i = 0; i < 8; i++) {
            float mx = fmaxf(fmaxf(s[i][0], s[i][1]), fmaxf(s[i][2], s[i][3]));
            mx = fmaxf(mx, __shfl_xor_sync(0xffffffffu, mx, 1));
            mx = fmaxf(mx, __shfl_xor_sync(0xffffffffu, mx, 2));
            mx = fmaxf(mx, __shfl_xor_sync(0xffffffffu, mx, 4));
            mx = fmaxf(mx, __shfl_xor_sync(0xffffffffu, mx, 8));
            float mn = fmaxf(m[i], mx);
            float al = __expf(m[i] - mn);
            float ls = 0.f;
#pragma unroll
            for (int j = 0; j < 4; j++) {
                float e = __expf(s[i][j] - mn);
                s[i][j] = e; ls += e;
            }
            ls += __shfl_xor_sync(0xffffffffu, ls, 1);
            ls += __shfl_xor_sync(0xffffffffu, ls, 2);
            ls += __shfl_xor_sync(0xffffffffu, ls, 4);
            ls += __shfl_xor_sync(0xffffffffu, ls, 8);
            l[i] = l[i]*al + ls; m[i] = mn;
#pragma unroll
            for (int j = 0; j < 4; j++) o[i][j] *= al;
        }
#pragma unroll
        for (int i = 0; i < 8; i++)
            *(float4*)&Ps[(ty*8+i)*68 + tx*4] = make_float4(s[i][0], s[i][1], s[i][2], s[i][3]);
        __syncthreads();
#pragma unroll 4
        for (int k = 0; k < 64; k++) {
            float4 vv = *(float4*)&Vs[k*68 + tx*4];
#pragma unroll
            for (int i = 0; i < 8; i++) {
                float pv = Ps[(ty*8+i)*68 + k];
                o[i][0] += pv*vv.x; o[i][1] += pv*vv.y;
                o[i][2] += pv*vv.z; o[i][3] += pv*vv.w;
            }
        }
    }
#pragma unroll
    for (int i = 0; i < 8; i++) {
        float inv = 1.f / l[i];
        size_t ob = ((size_t)(b*S_ + qt*128 + ty*8 + i))*(H_*HD_) + h*HD_ + tx*4;
        *(float4*)(O + ob) = make_float4(o[i][0]*inv, o[i][1]*inv, o[i][2]*inv, o[i][3]*inv);
    }
}

// ---------------- elementwise ----------------
__global__ void gatemul_kernel() {
    size_t i = (size_t)blockIdx.x * 256 + threadIdx.x;
    float4 g = ((float4*)g_gate)[i];
    float4 a = ((float4*)g_attn)[i];
    g.x = a.x / (1.f + __expf(-g.x));
    g.y = a.y / (1.f + __expf(-g.y));
    g.z = a.z / (1.f + __expf(-g.z));
    g.w = a.w / (1.f + __expf(-g.w));
    ((float4*)g_gate)[i] = g;
}
__global__ void silumul_kernel() {
    size_t i = (size_t)blockIdx.x * 256 + threadIdx.x;
    float4 a = ((float4*)g_h)[i];
    float4 b = ((float4*)g_h3)[i];
    a.x = a.x / (1.f + __expf(-a.x)) * b.x;
    a.y = a.y / (1.f + __expf(-a.y)) * b.y;
    a.z = a.z / (1.f + __expf(-a.z)) * b.z;
    a.w = a.w / (1.f + __expf(-a.w)) * b.w;
    ((float4*)g_h)[i] = a;
}

// ---------------- router + moe bookkeeping ----------------
__global__ void router_kernel(const float* __restrict__ rw) {
    int t = blockIdx.x;
    const float* x = g_xn2 + (size_t)t * D_;
    float le[8] = {0,0,0,0,0,0,0,0};
    for (int d = threadIdx.x; d < D_; d += 256) {
        float xv = x[d];
        const float4* r4 = (const float4*)(rw + (size_t)d * 8);
        float4 aa = r4[0], bb = r4[1];
        le[0] += xv*aa.x; le[1] += xv*aa.y; le[2] += xv*aa.z; le[3] += xv*aa.w;
        le[4] += xv*bb.x; le[5] += xv*bb.y; le[6] += xv*bb.z; le[7] += xv*bb.w;
    }
#pragma unroll
    for (int e = 0; e < 8; e++)
        for (int o = 16; o > 0; o >>= 1)
            le[e] += __shfl_xor_sync(0xffffffffu, le[e], o);
    __shared__ float smr[8][8];
    if ((threadIdx.x & 31) == 0)
#pragma unroll
        for (int e = 0; e < 8; e++) smr[threadIdx.x >> 5][e] = le[e];
    __syncthreads();
    if (threadIdx.x == 0) {
        float lg[8];
#pragma unroll
        for (int e = 0; e < 8; e++) {
            float s = 0.f;
            for (int w2 = 0; w2 < 8; w2++) s += smr[w2][e];
            lg[e] = s;
        }
        float mx = lg[0];
        for (int e = 1; e < 8; e++) mx = fmaxf(mx, lg[e]);
        float p[8], s = 0.f;
        for (int e = 0; e < 8; e++) { p[e] = expf(lg[e] - mx); s += p[e]; }
        float invs = 1.f / s;
        for (int e = 0; e < 8; e++) { p[e] *= invs; atomicAdd(&g_probsum[e], p[e]); }
        int i0 = 0;
        for (int e = 1; e < 8; e++) if (p[e] > p[i0]) i0 = e;
        int i1 = (i0 == 0) ? 1 : 0;
        for (int e = 0; e < 8; e++) if (e != i0 && p[e] > p[i1]) i1 = e;
        float tv0 = p[i0], tv1 = p[i1], s2 = tv0 + tv1;
        g_topi[t*2] = i0; g_topi[t*2+1] = i1;
        g_topv[t*2] = tv0/s2; g_topv[t*2+1] = tv1/s2;
        atomicAdd(&g_counts[i0], 1);
        atomicAdd(&g_counts[i1], 1);
    }
}
__global__ void zero_kernel() {
    int t = threadIdx.x;
    if (t < E_) { g_counts[t] = 0; g_cursor[t] = 0; g_probsum[t] = 0.f; }
}
__global__ void offsets_aux_kernel(float* __restrict__ aux_out) {
    if (threadIdx.x == 0) {
        int o = 0;
        for (int e = 0; e < E_; e++) { g_off[e] = o; o += g_counts[e]; }
        g_off[E_] = o;
        float aux = 0.f;
        for (int e = 0; e < E_; e++)
            aux += ((float)g_counts[e] / (NTOK*2.0f)) * (g_probsum[e] / (float)NTOK);
        aux_out[0] = 0.01f * (float)E_ * aux;
    }
}
__global__ void scatter_kernel() {
    int t = blockIdx.x * 256 + threadIdx.x;
    if (t >= NTOK) return;
#pragma unroll
    for (int k2 = 0; k2 < 2; k2++) {
        int e = g_topi[t*2+k2];
        int pos = g_off[e] + atomicAdd(&g_cursor[e], 1);
        g_permTok[pos] = t;
        g_permW[pos] = g_topv[t*2+k2];
        g_tokSlot[t*2+k2] = pos;
    }
}
__global__ void finaladd_kernel(float* __restrict__ out) {
    size_t i = (size_t)blockIdx.x * 256 + threadIdx.x;
    int t = (int)(i >> 10);
    int d = (int)(i & 1023);
    int s0 = g_tokSlot[t*2], s1 = g_tokSlot[t*2+1];
    out[i] = g_x1[i] + g_tmp[(size_t)s0*D_ + d] + g_tmp[(size_t)s1*D_ + d];
}

// ---------------- host launcher ----------------
extern "C" void kernel_launch(void* const* d_in, const int* in_sizes, int n_in,
                              void* d_out, int out_size) {
    const float* x        = (const float*)d_in[0];
    const float* attn_nw  = (const float*)d_in[1];
    const float* ffn_nw   = (const float*)d_in[2];
    const float* q_nw     = (const float*)d_in[3];
    const float* k_nw     = (const float*)d_in[4];
    const float* wq       = (const float*)d_in[5];
    const float* wk       = (const float*)d_in[6];
    const float* wv       = (const float*)d_in[7];
    const float* wo       = (const float*)d_in[8];
    const float* wg       = (const float*)d_in[9];
    const float* router_w = (const float*)d_in[10];
    const float* w1       = (const float*)d_in[11];
    const float* w3       = (const float*)d_in[12];
    const float* w2       = (const float*)d_in[13];
    float* out = (float*)d_out;

    float *p_xn, *p_q, *p_k, *p_v, *p_gate, *p_x1, *p_xn2, *p_attn;
    cudaGetSymbolAddress((void**)&p_xn, g_xn);
    cudaGetSymbolAddress((void**)&p_q, g_q);
    cudaGetSymbolAddress((void**)&p_k, g_k);
    cudaGetSymbolAddress((void**)&p_v, g_v);
    cudaGetSymbolAddress((void**)&p_gate, g_gate);
    cudaGetSymbolAddress((void**)&p_attn, g_attn);
    cudaGetSymbolAddress((void**)&p_x1, g_x1);
    cudaGetSymbolAddress((void**)&p_xn2, g_xn2);

    cudaFuncSetAttribute(gemm_plain<0,true>, cudaFuncAttributeMaxDynamicSharedMemorySize, SMEM_GEMM_S);
    cudaFuncSetAttribute(gemm_plain<1,true>, cudaFuncAttributeMaxDynamicSharedMemorySize, SMEM_GEMM_S);
    cudaFuncSetAttribute(attn_v2, cudaFuncAttributeMaxDynamicSharedMemorySize, SMEM_ATTN);

    rmsnorm_kernel<<<NTOK, 256>>>(x, attn_nw, p_xn, 1e-6f);
    gemm_plain<0,true><<<dim3(8,32), 256, SMEM_GEMM_S>>>(p_xn, wq, p_q, nullptr, 1024, 1024, NTOK);
    gemm_plain<0,true><<<dim3(2,32), 256, SMEM_GEMM_S>>>(p_xn, wk, p_k, nullptr, 256, 1024, NTOK);
    gemm_plain<0,true><<<dim3(2,32), 256, SMEM_GEMM_S>>>(p_xn, wv, p_v, nullptr, 256, 1024, NTOK);
    gemm_plain<0,true><<<dim3(8,32), 256, SMEM_GEMM_S>>>(p_xn, wg, p_gate, nullptr, 1024, 1024, NTOK);
    qkrope_kernel<<<(NTOK*H_*32)/256, 256>>>(p_q, q_nw, H_);
    qkrope_kernel<<<(NTOK*KH_*32)/256, 256>>>(p_k, k_nw, KH_);
    attn_v2<<<dim3(S_/128, H_, B_), 256, SMEM_ATTN>>>(p_q, p_k, p_v, p_attn);
    gatemul_kernel<<<(NTOK*1024/4)/256, 256>>>();
    gemm_plain<1,true><<<dim3(8,32), 256, SMEM_GEMM_S>>>(p_gate, wo, p_x1, x, 1024, 1024, NTOK);
    rmsnorm_kernel<<<NTOK, 256>>>(p_x1, ffn_nw, p_xn2, 1e-6f);
    zero_kernel<<<1, 32>>>();
    router_kernel<<<NTOK, 256>>>(router_w);
    offsets_aux_kernel<<<1, 32>>>(out + (size_t)NTOK*D_);
    scatter_kernel<<<NTOK/256, 256>>>();
    moe13_gemm<<<dim3(FF_/128, NSLOT/128, 16), 256, SMEM_GEMM>>>(w1, w3);
    silumul_kernel<<<((size_t)NSLOT*FF_/4)/256, 256>>>();
    moe2_gemm<<<dim3(D_/128, NSLOT/128, 8), 256, SMEM_GEMM>>>(w2);
    finaladd_kernel<<<(NTOK*1024)/256, 256>>>(out);
}

// round 4
// speedup vs baseline: 5.7079x; 1.0205x over previous
#include <cuda_runtime.h>
#include <math.h>
#include <stdint.h>

#define B_ 2
#define S_ 2048
#define D_ 1024
#define H_ 16
#define KH_ 4
#define HD_ 64
#define E_ 8
#define FF_ 2048
#define NTOK (B_*S_)
#define NSLOT (NTOK*2)
#define NEG_BIG -3.0e38f

#define BM 128
#define BN 128
#define LDA 36
#define LDB 136
#define PLANE (BM*LDA + 32*LDB)          // 8960 floats
#define SMEM_GEMM   (2*PLANE*4)          // 71680
#define SMEM_GEMM_S (4*PLANE*4)          // 143360
#define SMEM_ATTN   ((64*132 + 64*68 + 64*68 + 128*68)*4)

__device__ float g_xn  [NTOK*D_];
__device__ float g_q   [NTOK*H_*HD_];
__device__ float g_k   [NTOK*KH_*HD_];
__device__ float g_v   [NTOK*KH_*HD_];
__device__ float g_gate[NTOK*H_*HD_];
__device__ float g_attn[NTOK*H_*HD_];
__device__ float g_x1  [NTOK*D_];
__device__ float g_xn2 [NTOK*D_];
__device__ float g_h   [(size_t)NSLOT*FF_];
__device__ float g_h3  [(size_t)NSLOT*FF_];
__device__ float g_tmp [(size_t)NSLOT*D_];
__device__ int   g_topi[NTOK*2];
__device__ float g_topv[NTOK*2];
__device__ int   g_permTok[NSLOT];
__device__ float g_permW  [NSLOT];
__device__ int   g_tokSlot[NTOK*2];
__device__ int   g_counts[E_];
__device__ int   g_off   [E_+1];
__device__ int   g_cursor[E_];
__device__ float g_probsum[E_];

__device__ __forceinline__ unsigned f2tf(float v) {
    unsigned r; asm("cvt.rna.tf32.f32 %0, %1;" : "=r"(r) : "f"(v)); return r;
}
__device__ __forceinline__ void mma_tf32(float* d, const unsigned* a, unsigned b0, unsigned b1) {
    asm volatile("mma.sync.aligned.m16n8k8.row.col.f32.tf32.tf32.f32 "
        "{%0,%1,%2,%3}, {%4,%5,%6,%7}, {%8,%9}, {%0,%1,%2,%3};"
        : "+f"(d[0]), "+f"(d[1]), "+f"(d[2]), "+f"(d[3])
        : "r"(a[0]), "r"(a[1]), "r"(a[2]), "r"(a[3]), "r"(b0), "r"(b1));
}

// tf32 MMA GEMM 128x128x32, 256 thr, double-buffered smem.
// EPI: 0 plain, 1 C=X+acc, 3 C=X[row]*acc
template<int EPI, bool SPLIT>
__device__ __forceinline__ void gemm_core(
    const float* __restrict__ A, const float* __restrict__ B,
    float* __restrict__ C, const float* __restrict__ X,
    int N, int K, int ldc, int rowstart, int rowend,
    const int* __restrict__ rowmap, int bx, int by)
{
    extern __shared__ float sm[];
    const int SS = PLANE * (SPLIT ? 2 : 1);
    int tid = threadIdx.x;
    int rowbase = rowstart + by*BM;
    if (rowbase >= rowend) return;
    int nbase = bx*BN;
    int k4 = tid & 7, n4 = tid & 31;
    const float* aP[4]; bool av[4];
#pragma unroll
    for (int i = 0; i < 4; i++) {
        int grow = rowbase + (tid >> 3) + 32*i;
        av[i] = grow < rowend;
        int ar = av[i] ? (rowmap ? rowmap[grow] : grow)
                       : (rowmap ? rowmap[rowstart] : rowstart);
        aP[i] = A + (size_t)ar*K + k4*4;
    }
    const float* bP = B + (size_t)(tid>>5)*N + nbase + n4*4;
    int lane = tid & 31, gp = lane >> 2, t4 = lane & 3;
    int w = tid >> 5, mb = (w & 3)*32, nb = (w >> 2)*64;

    float acc[2][8][4];
#pragma unroll
    for (int a = 0; a < 2; a++)
#pragma unroll
        for (int b = 0; b < 8; b++)
#pragma unroll
            for (int c = 0; c < 4; c++) acc[a][b][c] = 0.f;

    float4 va[4], vb[4];
#pragma unroll
    for (int i = 0; i < 4; i++) {
        va[i] = av[i] ? *(const float4*)aP[i] : make_float4(0,0,0,0);
        vb[i] = *(const float4*)(bP + (size_t)(8*i)*N);
    }
    int nkt = K >> 5;

    auto stage = [&](float* base) {
        float* Ah = base; float* Bh = base + BM*LDA;
        float* Al = Bh + 32*LDB; float* Bl = Al + BM*LDA;
#pragma unroll
        for (int i = 0; i < 4; i++) {
            int m = (tid >> 3) + 32*i;
            float vv[4] = {va[i].x, va[i].y, va[i].z, va[i].w};
            float4 hi, lo; float* hp = &hi.x; float* lp = &lo.x;
#pragma unroll
            for (int j = 0; j < 4; j++) {
                unsigned h2 = f2tf(vv[j]);
                hp[j] = __uint_as_float(h2);
                if (SPLIT) lp[j] = __uint_as_float(f2tf(vv[j] - __uint_as_float(h2)));
            }
            *(float4*)(Ah + m*LDA + k4*4) = hi;
            if (SPLIT) *(float4*)(Al + m*LDA + k4*4) = lo;
            int kr = (tid >> 5) + 8*i;
            float bv[4] = {vb[i].x, vb[i].y, vb[i].z, vb[i].w};
#pragma unroll
            for (int j = 0; j < 4; j++) {
                unsigned h2 = f2tf(bv[j]);
                hp[j] = __uint_as_float(h2);
                if (SPLIT) lp[j] = __uint_as_float(f2tf(bv[j] - __uint_as_float(h2)));
            }
            *(float4*)(Bh + kr*LDB + n4*4) = hi;
            if (SPLIT) *(float4*)(Bl + kr*LDB + n4*4) = lo;
        }
    };
    auto compute = [&](float* base) {
        float* Ah = base; float* Bh = base + BM*LDA;
        float* Al = Bh + 32*LDB; float* Bl = Al + BM*LDA;
#pragma unroll
        for (int ks = 0; ks < 4; ks++) {
            int kf = ks*8 + t4;
            unsigned a[2][4], al[2][4];
#pragma unroll
            for (int mt = 0; mt < 2; mt++) {
                int r = mb + mt*16 + gp;
                a[mt][0] = __float_as_uint(Ah[r*LDA + kf]);
                a[mt][1] = __float_as_uint(Ah[(r+8)*LDA + kf]);
                a[mt][2] = __float_as_uint(Ah[r*LDA + kf + 4]);
                a[mt][3] = __float_as_uint(Ah[(r+8)*LDA + kf + 4]);
                if (SPLIT) {
                    al[mt][0] = __float_as_uint(Al[r*LDA + kf]);
                    al[mt][1] = __float_as_uint(Al[(r+8)*LDA + kf]);
                    al[mt][2] = __float_as_uint(Al[r*LDA + kf + 4]);
                    al[mt][3] = __float_as_uint(Al[(r+8)*LDA + kf + 4]);
                }
            }
#pragma unroll
            for (int nt = 0; nt < 8; nt++) {
                int c = nb + nt*8 + gp;
                unsigned b0 = __float_as_uint(Bh[kf*LDB + c]);
                unsigned b1 = __float_as_uint(Bh[(kf+4)*LDB + c]);
#pragma unroll
                for (int mt = 0; mt < 2; mt++) mma_tf32(acc[mt][nt], a[mt], b0, b1);
                if (SPLIT) {
                    unsigned c0 = __float_as_uint(Bl[kf*LDB + c]);
                    unsigned c1 = __float_as_uint(Bl[(kf+4)*LDB + c]);
#pragma unroll
                    for (int mt = 0; mt < 2; mt++) {
                        mma_tf32(acc[mt][nt], a[mt], c0, c1);
                        mma_tf32(acc[mt][nt], al[mt], b0, b1);
                    }
                }
            }
        }
    };

    stage(sm);
    __syncthreads();
    for (int kt = 0; kt < nkt; kt++) {
        if (kt + 1 < nkt) {
#pragma unroll
            for (int i = 0; i < 4; i++) {
                va[i] = av[i] ? *(const float4*)(aP[i] + (kt+1)*32) : make_float4(0,0,0,0);
                vb[i] = *(const float4*)(bP + (size_t)((kt+1)*32 + 8*i)*N);
            }
        }
        compute(sm + (kt & 1)*SS);
        if (kt + 1 < nkt) stage(sm + ((kt+1) & 1)*SS);
        __syncthreads();
    }

#pragma unroll
    for (int mt = 0; mt < 2; mt++) {
        int r0 = rowbase + mb + mt*16 + gp;
        int r1 = r0 + 8;
        float s0 = 0.f, s1 = 0.f;
        if (EPI == 3) {
            s0 = (r0 < rowend) ? X[r0] : 0.f;
            s1 = (r1 < rowend) ? X[r1] : 0.f;
        }
#pragma unroll
        for (int nt = 0; nt < 8; nt++) {
            int col = nbase + nb + nt*8 + t4*2;
            if (r0 < rowend) {
                float2 v = make_float2(acc[mt][nt][0], acc[mt][nt][1]);
                if (EPI == 1) { float2 xr = *(const float2*)(X + (size_t)r0*ldc + col); v.x += xr.x; v.y += xr.y; }
                if (EPI == 3) { v.x *= s0; v.y *= s0; }
                *(float2*)(C + (size_t)r0*ldc + col) = v;
            }
            if (r1 < rowend) {
                float2 v = make_float2(acc[mt][nt][2], acc[mt][nt][3]);
                if (EPI == 1) { float2 xr = *(const float2*)(X + (size_t)r1*ldc + col); v.x += xr.x; v.y += xr.y; }
                if (EPI == 3) { v.x *= s1; v.y *= s1; }
                *(float2*)(C + (size_t)r1*ldc + col) = v;
            }
        }
    }
}

template<int EPI, bool SPLIT>
__global__ void __launch_bounds__(256) gemm_plain(
    const float* __restrict__ A, const float* __restrict__ B,
    float* __restrict__ C, const float* __restrict__ X, int N, int K, int M)
{
    gemm_core<EPI,SPLIT>(A, B, C, X, N, K, N, 0, M, nullptr, blockIdx.x, blockIdx.y);
}

// fused wq|wk|wv|wg projection: bx 0-7 wq, 8-9 wk, 10-11 wv, 12-19 wg
__global__ void __launch_bounds__(256) proj_gemm(
    const float* __restrict__ wq, const float* __restrict__ wk,
    const float* __restrict__ wv, const float* __restrict__ wg)
{
    int bx = blockIdx.x;
    const float* Bp; float* C; int N; int lbx;
    if (bx < 8)       { Bp = wq; C = g_q;    N = 1024; lbx = bx; }
    else if (bx < 10) { Bp = wk; C = g_k;    N = 256;  lbx = bx - 8; }
    else if (bx < 12) { Bp = wv; C = g_v;    N = 256;  lbx = bx - 10; }
    else              { Bp = wg; C = g_gate; N = 1024; lbx = bx - 12; }
    gemm_core<0,true>(g_xn, Bp, C, nullptr, N, 1024, N, 0, NTOK, nullptr, lbx, blockIdx.y);
}

__global__ void __launch_bounds__(256) moe13_gemm(
    const float* __restrict__ w1, const float* __restrict__ w3)
{
    int z = blockIdx.z, e = z >> 1;
    const float* B = ((z & 1) ? w3 : w1) + (size_t)e*D_*FF_;
    float* C = (z & 1) ? g_h3 : g_h;
    gemm_core<0,false>(g_xn2, B, C, nullptr, FF_, D_, FF_,
                       g_off[e], g_off[e+1], g_permTok, blockIdx.x, blockIdx.y);
}

__global__ void __launch_bounds__(256) moe2_gemm(const float* __restrict__ w2)
{
    int e = blockIdx.z;
    gemm_core<3,false>(g_h, w2 + (size_t)e*FF_*D_, g_tmp, g_permW, D_, FF_, D_,
                       g_off[e], g_off[e+1], nullptr, blockIdx.x, blockIdx.y);
}

// ---------------- rmsnorm ----------------
__global__ void rmsnorm_kernel(const float* __restrict__ x, const float* __restrict__ w,
                               float* __restrict__ out, float eps) {
    int t = blockIdx.x;
    const float4* xr = (const float4*)(x + (size_t)t * D_);
    float4 v = xr[threadIdx.x];
    float ss = v.x*v.x + v.y*v.y + v.z*v.z + v.w*v.w;
    __shared__ float smr[8];
    for (int o = 16; o > 0; o >>= 1) ss += __shfl_xor_sync(0xffffffffu, ss, o);
    if ((threadIdx.x & 31) == 0) smr[threadIdx.x >> 5] = ss;
    __syncthreads();
    if (threadIdx.x < 8) {
        float s2 = smr[threadIdx.x];
        for (int o = 4; o > 0; o >>= 1) s2 += __shfl_xor_sync(0xffu, s2, o);
        if (threadIdx.x == 0) smr[0] = s2;
    }
    __syncthreads();
    float sc = rsqrtf(smr[0] * (1.0f / D_) + eps);
    float4 wv = ((const float4*)w)[threadIdx.x];
    ((float4*)(out + (size_t)t * D_))[threadIdx.x] =
        make_float4(v.x*sc*wv.x, v.y*sc*wv.y, v.z*sc*wv.z, v.w*sc*wv.w);
}

// ---------------- q/k rmsnorm + rope ----------------
__global__ void qkrope_kernel(float* buf, const float* __restrict__ w, int nheads) {
    int wid = (blockIdx.x * blockDim.x + threadIdx.x) >> 5;
    int lane = threadIdx.x & 31;
    int t = wid / nheads, h = wid - t * nheads;
    int pos = t & (S_ - 1);
    size_t base = (size_t)t * nheads * HD_ + h * HD_;
    float v0 = buf[base + 2*lane], v1 = buf[base + 2*lane + 1];
    float ss = v0*v0 + v1*v1;
    for (int o = 16; o > 0; o >>= 1) ss += __shfl_xor_sync(0xffffffffu, ss, o);
    float sc = rsqrtf(ss * (1.0f / HD_) + 1e-5f);
    float a  = v0 * sc * w[2*lane];
    float b2 = v1 * sc * w[2*lane + 1];
    float inv = expf(-(float)lane * (2.0f / HD_) * 9.210340371976184f);
    float ang = (float)pos * inv;
    float cs = cosf(ang), sn = sinf(ang);
    buf[base + 2*lane]     = a*cs - b2*sn;
    buf[base + 2*lane + 1] = a*sn + b2*cs;
}

// ---------------- flash attention: BQ=128 BK=64, vectorized PV --------------
__global__ void __launch_bounds__(256) attn_v2(
    const float* __restrict__ Q, const float* __restrict__ Kb,
    const float* __restrict__ Vb, float* __restrict__ O)
{
    extern __shared__ float smA[];
    float* QsT = smA;                // [64][132] (d,q)
    float* KsT = QsT + 64*132;       // [64][68]  (d,k)
    float* Vs  = KsT + 64*68;        // [64][68]  (k,d)
    float* Ps  = Vs  + 64*68;        // [128][68] (q,k)
    int qt = blockIdx.x, h = blockIdx.y, b = blockIdx.z;
    int kh = h >> 2;
    int tid = threadIdx.x;
    int ty = tid >> 4, tx = tid & 15;

#pragma unroll
    for (int i = 0; i < 8; i++) {
        int id = tid + i*256;
        int q = id >> 4, d4 = id & 15;
        float4 v = *(const float4*)(Q + ((size_t)(b*S_ + qt*128 + q))*(H_*HD_) + h*HD_ + d4*4);
        QsT[(d4*4+0)*132 + q] = v.x * 0.125f;
        QsT[(d4*4+1)*132 + q] = v.y * 0.125f;
        QsT[(d4*4+2)*132 + q] = v.z * 0.125f;
        QsT[(d4*4+3)*132 + q] = v.w * 0.125f;
    }

    float m[8], l[8], o[8][4];
#pragma unroll
    for (int i = 0; i < 8; i++) {
        m[i] = NEG_BIG; l[i] = 0.f;
#pragma unroll
        for (int j = 0; j < 4; j++) o[i][j] = 0.f;
    }
    int nkt = 2*(qt+1);

    for (int kt = 0; kt < nkt; kt++) {
        __syncthreads();
#pragma unroll
        for (int i = 0; i < 4; i++) {
            int id = tid + i*256;
            int k = id >> 4, d4 = id & 15;
            size_t gb = ((size_t)(b*S_ + kt*64 + k))*(KH_*HD_) + kh*HD_ + d4*4;
            float4 kv = *(const float4*)(Kb + gb);
            KsT[(d4*4+0)*68 + k] = kv.x;
            KsT[(d4*4+1)*68 + k] = kv.y;
            KsT[(d4*4+2)*68 + k] = kv.z;
            KsT[(d4*4+3)*68 + k] = kv.w;
            *(float4*)&Vs[k*68 + d4*4] = *(const float4*)(Vb + gb);
        }
        __syncthreads();

        float s[8][4];
#pragma unroll
        for (int i = 0; i < 8; i++)
#pragma unroll
            for (int j = 0; j < 4; j++) s[i][j] = 0.f;
#pragma unroll 4
        for (int d = 0; d < 64; d++) {
            float4 q0 = *(float4*)&QsT[d*132 + ty*8];
            float4 q1 = *(float4*)&QsT[d*132 + ty*8 + 4];
            float4 kk = *(float4*)&KsT[d*68 + tx*4];
            float qa[8] = {q0.x,q0.y,q0.z,q0.w,q1.x,q1.y,q1.z,q1.w};
            float kb2[4] = {kk.x,kk.y,kk.z,kk.w};
#pragma unroll
            for (int i = 0; i < 8; i++)
#pragma unroll
                for (int j = 0; j < 4; j++) s[i][j] += qa[i]*kb2[j];
        }
        int qg0 = qt*128 + ty*8;
        int kg0 = kt*64 + tx*4;
#pragma unroll
        for (int i = 0; i < 8; i++)
#pragma unroll
            for (int j = 0; j < 4; j++)
                if (kg0 + j > qg0 + i) s[i][j] = NEG_BIG;

#pragma unroll
        for (int i = 0; i < 8; i++) {
            float mx = fmaxf(fmaxf(s[i][0], s[i][1]), fmaxf(s[i][2], s[i][3]));
            mx = fmaxf(mx, __shfl_xor_sync(0xffffffffu, mx, 1));
            mx = fmaxf(mx, __shfl_xor_sync(0xffffffffu, mx, 2));
            mx = fmaxf(mx, __shfl_xor_sync(0xffffffffu, mx, 4));
            mx = fmaxf(mx, __shfl_xor_sync(0xffffffffu, mx, 8));
            float mn = fmaxf(m[i], mx);
            float al = __expf(m[i] - mn);
            float ls = 0.f;
#pragma unroll
            for (int j = 0; j < 4; j++) {
                float e = __expf(s[i][j] - mn);
                s[i][j] = e; ls += e;
            }
            ls += __shfl_xor_sync(0xffffffffu, ls, 1);
            ls += __shfl_xor_sync(0xffffffffu, ls, 2);
            ls += __shfl_xor_sync(0xffffffffu, ls, 4);
            ls += __shfl_xor_sync(0xffffffffu, ls, 8);
            l[i] = l[i]*al + ls; m[i] = mn;
#pragma unroll
            for (int j = 0; j < 4; j++) o[i][j] *= al;
        }
#pragma unroll
        for (int i = 0; i < 8; i++)
            *(float4*)&Ps[(ty*8+i)*68 + tx*4] = make_float4(s[i][0], s[i][1], s[i][2], s[i][3]);
        __syncthreads();
#pragma unroll 2
        for (int k4 = 0; k4 < 16; k4++) {
            float4 vv0 = *(float4*)&Vs[(k4*4+0)*68 + tx*4];
            float4 vv1 = *(float4*)&Vs[(k4*4+1)*68 + tx*4];
            float4 vv2 = *(float4*)&Vs[(k4*4+2)*68 + tx*4];
            float4 vv3 = *(float4*)&Vs[(k4*4+3)*68 + tx*4];
#pragma unroll
            for (int i = 0; i < 8; i++) {
                float4 p = *(float4*)&Ps[(ty*8+i)*68 + k4*4];
                o[i][0] += p.x*vv0.x + p.y*vv1.x + p.z*vv2.x + p.w*vv3.x;
                o[i][1] += p.x*vv0.y + p.y*vv1.y + p.z*vv2.y + p.w*vv3.y;
                o[i][2] += p.x*vv0.z + p.y*vv1.z + p.z*vv2.z + p.w*vv3.z;
                o[i][3] += p.x*vv0.w + p.y*vv1.w + p.z*vv2.w + p.w*vv3.w;
            }
        }
    }
#pragma unroll
    for (int i = 0; i < 8; i++) {
        float inv = 1.f / l[i];
        size_t ob = ((size_t)(b*S_ + qt*128 + ty*8 + i))*(H_*HD_) + h*HD_ + tx*4;
        *(float4*)(O + ob) = make_float4(o[i][0]*inv, o[i][1]*inv, o[i][2]*inv, o[i][3]*inv);
    }
}

// ---------------- elementwise ----------------
__global__ void gatemul_kernel() {
    size_t i = (size_t)blockIdx.x * 256 + threadIdx.x;
    float4 g = ((float4*)g_gate)[i];
    float4 a = ((float4*)g_attn)[i];
    g.x = a.x / (1.f + __expf(-g.x));
    g.y = a.y / (1.f + __expf(-g.y));
    g.z = a.z / (1.f + __expf(-g.z));
    g.w = a.w / (1.f + __expf(-g.w));
    ((float4*)g_gate)[i] = g;
}
__global__ void silumul_kernel() {
    size_t i = (size_t)blockIdx.x * 256 + threadIdx.x;
    float4 a = ((float4*)g_h)[i];
    float4 b = ((float4*)g_h3)[i];
    a.x = a.x / (1.f + __expf(-a.x)) * b.x;
    a.y = a.y / (1.f + __expf(-a.y)) * b.y;
    a.z = a.z / (1.f + __expf(-a.z)) * b.z;
    a.w = a.w / (1.f + __expf(-a.w)) * b.w;
    ((float4*)g_h)[i] = a;
}

// ---------------- router + moe bookkeeping ----------------
__global__ void router_kernel(const float* __restrict__ rw) {
    int t = blockIdx.x;
    const float* x = g_xn2 + (size_t)t * D_;
    float le[8] = {0,0,0,0,0,0,0,0};
    for (int d = threadIdx.x; d < D_; d += 256) {
        float xv = x[d];
        const float4* r4 = (const float4*)(rw + (size_t)d * 8);
        float4 aa = r4[0], bb = r4[1];
        le[0] += xv*aa.x; le[1] += xv*aa.y; le[2] += xv*aa.z; le[3] += xv*aa.w;
        le[4] += xv*bb.x; le[5] += xv*bb.y; le[6] += xv*bb.z; le[7] += xv*bb.w;
    }
#pragma unroll
    for (int e = 0; e < 8; e++)
        for (int o = 16; o > 0; o >>= 1)
            le[e] += __shfl_xor_sync(0xffffffffu, le[e], o);
    __shared__ float smr[8][8];
    if ((threadIdx.x & 31) == 0)
#pragma unroll
        for (int e = 0; e < 8; e++) smr[threadIdx.x >> 5][e] = le[e];
    __syncthreads();
    if (threadIdx.x == 0) {
        float lg[8];
#pragma unroll
        for (int e = 0; e < 8; e++) {
            float s = 0.f;
            for (int w2 = 0; w2 < 8; w2++) s += smr[w2][e];
            lg[e] = s;
        }
        float mx = lg[0];
        for (int e = 1; e < 8; e++) mx = fmaxf(mx, lg[e]);
        float p[8], s = 0.f;
        for (int e = 0; e < 8; e++) { p[e] = expf(lg[e] - mx); s += p[e]; }
        float invs = 1.f / s;
        for (int e = 0; e < 8; e++) { p[e] *= invs; atomicAdd(&g_probsum[e], p[e]); }
        int i0 = 0;
        for (int e = 1; e < 8; e++) if (p[e] > p[i0]) i0 = e;
        int i1 = (i0 == 0) ? 1 : 0;
        for (int e = 0; e < 8; e++) if (e != i0 && p[e] > p[i1]) i1 = e;
        float tv0 = p[i0], tv1 = p[i1], s2 = tv0 + tv1;
        g_topi[t*2] = i0; g_topi[t*2+1] = i1;
        g_topv[t*2] = tv0/s2; g_topv[t*2+1] = tv1/s2;
        atomicAdd(&g_counts[i0], 1);
        atomicAdd(&g_counts[i1], 1);
    }
}
__global__ void zero_kernel() {
    int t = threadIdx.x;
    if (t < E_) { g_counts[t] = 0; g_cursor[t] = 0; g_probsum[t] = 0.f; }
}
__global__ void offsets_aux_kernel(float* __restrict__ aux_out) {
    if (threadIdx.x == 0) {
        int o = 0;
        for (int e = 0; e < E_; e++) { g_off[e] = o; o += g_counts[e]; }
        g_off[E_] = o;
        float aux = 0.f;
        for (int e = 0; e < E_; e++)
            aux += ((float)g_counts[e] / (NTOK*2.0f)) * (g_probsum[e] / (float)NTOK);
        aux_out[0] = 0.01f * (float)E_ * aux;
    }
}
__global__ void scatter_kernel() {
    int t = blockIdx.x * 256 + threadIdx.x;
    if (t >= NTOK) return;
#pragma unroll
    for (int k2 = 0; k2 < 2; k2++) {
        int e = g_topi[t*2+k2];
        int pos = g_off[e] + atomicAdd(&g_cursor[e], 1);
        g_permTok[pos] = t;
        g_permW[pos] = g_topv[t*2+k2];
        g_tokSlot[t*2+k2] = pos;
    }
}
__global__ void finaladd_kernel(float* __restrict__ out) {
    size_t i = (size_t)blockIdx.x * 256 + threadIdx.x;
    int t = (int)(i >> 10);
    int d = (int)(i & 1023);
    int s0 = g_tokSlot[t*2], s1 = g_tokSlot[t*2+1];
    out[i] = g_x1[i] + g_tmp[(size_t)s0*D_ + d] + g_tmp[(size_t)s1*D_ + d];
}

// ---------------- host launcher ----------------
extern "C" void kernel_launch(void* const* d_in, const int* in_sizes, int n_in,
                              void* d_out, int out_size) {
    const float* x        = (const float*)d_in[0];
    const float* attn_nw  = (const float*)d_in[1];
    const float* ffn_nw   = (const float*)d_in[2];
    const float* q_nw     = (const float*)d_in[3];
    const float* k_nw     = (const float*)d_in[4];
    const float* wq       = (const float*)d_in[5];
    const float* wk       = (const float*)d_in[6];
    const float* wv       = (const float*)d_in[7];
    const float* wo       = (const float*)d_in[8];
    const float* wg       = (const float*)d_in[9];
    const float* router_w = (const float*)d_in[10];
    const float* w1       = (const float*)d_in[11];
    const float* w3       = (const float*)d_in[12];
    const float* w2       = (const float*)d_in[13];
    float* out = (float*)d_out;

    float *p_xn, *p_q, *p_k, *p_v, *p_gate, *p_x1, *p_xn2, *p_attn;
    cudaGetSymbolAddress((void**)&p_xn, g_xn);
    cudaGetSymbolAddress((void**)&p_q, g_q);
    cudaGetSymbolAddress((void**)&p_k, g_k);
    cudaGetSymbolAddress((void**)&p_v, g_v);
    cudaGetSymbolAddress((void**)&p_gate, g_gate);
    cudaGetSymbolAddress((void**)&p_attn, g_attn);
    cudaGetSymbolAddress((void**)&p_x1, g_x1);
    cudaGetSymbolAddress((void**)&p_xn2, g_xn2);

    cudaFuncSetAttribute(proj_gemm, cudaFuncAttributeMaxDynamicSharedMemorySize, SMEM_GEMM_S);
    cudaFuncSetAttribute(gemm_plain<1,true>, cudaFuncAttributeMaxDynamicSharedMemorySize, SMEM_GEMM_S);
    cudaFuncSetAttribute(moe13_gemm, cudaFuncAttributeMaxDynamicSharedMemorySize, SMEM_GEMM);
    cudaFuncSetAttribute(moe2_gemm, cudaFuncAttributeMaxDynamicSharedMemorySize, SMEM_GEMM);
    cudaFuncSetAttribute(attn_v2, cudaFuncAttributeMaxDynamicSharedMemorySize, SMEM_ATTN);

    rmsnorm_kernel<<<NTOK, 256>>>(x, attn_nw, p_xn, 1e-6f);
    proj_gemm<<<dim3(20,32), 256, SMEM_GEMM_S>>>(wq, wk, wv, wg);
    qkrope_kernel<<<(NTOK*H_*32)/256, 256>>>(p_q, q_nw, H_);
    qkrope_kernel<<<(NTOK*KH_*32)/256, 256>>>(p_k, k_nw, KH_);
    attn_v2<<<dim3(S_/128, H_, B_), 256, SMEM_ATTN>>>(p_q, p_k, p_v, p_attn);
    gatemul_kernel<<<(NTOK*1024/4)/256, 256>>>();
    gemm_plain<1,true><<<dim3(8,32), 256, SMEM_GEMM_S>>>(p_gate, wo, p_x1, x, 1024, 1024, NTOK);
    rmsnorm_kernel<<<NTOK, 256>>>(p_x1, ffn_nw, p_xn2, 1e-6f);
    zero_kernel<<<1, 32>>>();
    router_kernel<<<NTOK, 256>>>(router_w);
    offsets_aux_kernel<<<1, 32>>>(out + (size_t)NTOK*D_);
    scatter_kernel<<<NTOK/256, 256>>>();
    moe13_gemm<<<dim3(FF_/128, 32, 16), 256, SMEM_GEMM>>>(w1, w3);
    silumul_kernel<<<((size_t)NSLOT*FF_/4)/256, 256>>>();
    moe2_gemm<<<dim3(D_/128, 32, 8), 256, SMEM_GEMM>>>(w2);
    finaladd_kernel<<<(NTOK*1024)/256, 256>>>(out);
}

// round 5
// speedup vs baseline: 5.8463x; 1.0243x over previous
#include <cuda_runtime.h>
#include <cuda_bf16.h>
#include <math.h>
#include <stdint.h>

#define B_ 2
#define S_ 2048
#define D_ 1024
#define H_ 16
#define KH_ 4
#define HD_ 64
#define E_ 8
#define FF_ 2048
#define NTOK (B_*S_)
#define NSLOT (NTOK*2)
#define NEG_BIG -3.0e38f

#define BM 128
#define BN 128
#define LDA 36
#define LDB 136
#define PLANE (BM*LDA + 32*LDB)
#define SMEM_GEMM_S (4*PLANE*4)
#define SMEM_ATTN   ((64*132 + 64*68 + 64*68 + 128*68)*4)
#define PITCH 20                      // b32 words per 32-bf16 k-row (16 + 4 pad)
#define PLANE_BF (256*PITCH)          // A[128][PITCH] + B[128][PITCH]

__device__ float g_xn  [NTOK*D_];
__device__ float g_q   [NTOK*H_*HD_];
__device__ float g_k   [NTOK*KH_*HD_];
__device__ float g_v   [NTOK*KH_*HD_];
__device__ float g_gate[NTOK*H_*HD_];
__device__ float g_attn[NTOK*H_*HD_];
__device__ float g_x1  [NTOK*D_];
__device__ float g_xn2 [NTOK*D_];
__device__ float g_h   [(size_t)NSLOT*FF_];
__device__ float g_h3  [(size_t)NSLOT*FF_];
__device__ float g_tmp [(size_t)NSLOT*D_];
__device__ __nv_bfloat16 g_w1T[(size_t)E_*FF_*D_];   // [E][FF][D]
__device__ __nv_bfloat16 g_w3T[(size_t)E_*FF_*D_];   // [E][FF][D]
__device__ __nv_bfloat16 g_w2T[(size_t)E_*D_*FF_];   // [E][D][FF]
__device__ int   g_topi[NTOK*2];
__device__ float g_topv[NTOK*2];
__device__ int   g_permTok[NSLOT];
__device__ float g_permW  [NSLOT];
__device__ int   g_tokSlot[NTOK*2];
__device__ int   g_counts[E_];
__device__ int   g_off   [E_+1];
__device__ int   g_cursor[E_];
__device__ float g_probsum[E_];

__device__ __forceinline__ unsigned f2tf(float v) {
    unsigned r; asm("cvt.rna.tf32.f32 %0, %1;" : "=r"(r) : "f"(v)); return r;
}
__device__ __forceinline__ void mma_tf32(float* d, const unsigned* a, unsigned b0, unsigned b1) {
    asm volatile("mma.sync.aligned.m16n8k8.row.col.f32.tf32.tf32.f32 "
        "{%0,%1,%2,%3}, {%4,%5,%6,%7}, {%8,%9}, {%0,%1,%2,%3};"
        : "+f"(d[0]), "+f"(d[1]), "+f"(d[2]), "+f"(d[3])
        : "r"(a[0]), "r"(a[1]), "r"(a[2]), "r"(a[3]), "r"(b0), "r"(b1));
}
__device__ __forceinline__ unsigned pack_bf(float lo, float hi) {
    unsigned r; asm("cvt.rn.bf16x2.f32 %0, %1, %2;" : "=r"(r) : "f"(hi), "f"(lo)); return r;
}
__device__ __forceinline__ void mma_bf16(float* d, const unsigned* a, unsigned b0, unsigned b1) {
    asm volatile("mma.sync.aligned.m16n8k16.row.col.f32.bf16.bf16.f32 "
        "{%0,%1,%2,%3}, {%4,%5,%6,%7}, {%8,%9}, {%0,%1,%2,%3};"
        : "+f"(d[0]), "+f"(d[1]), "+f"(d[2]), "+f"(d[3])
        : "r"(a[0]), "r"(a[1]), "r"(a[2]), "r"(a[3]), "r"(b0), "r"(b1));
}

// ======= split-tf32 MMA GEMM 128x128x32 (precision-critical path) =======
// EPI: 0 plain, 1 C=X+acc
template<int EPI>
__device__ __forceinline__ void gemm_core(
    const float* __restrict__ A, const float* __restrict__ B,
    float* __restrict__ C, const float* __restrict__ X,
    int N, int K, int ldc, int M, int bx, int by)
{
    extern __shared__ float sm[];
    const int SS = PLANE*2;
    int tid = threadIdx.x;
    int rowbase = by*BM;
    int nbase = bx*BN;
    int k4 = tid & 7, n4 = tid & 31;
    const float* aP[4];
#pragma unroll
    for (int i = 0; i < 4; i++)
        aP[i] = A + (size_t)(rowbase + (tid>>3) + 32*i)*K + k4*4;
    const float* bP = B + (size_t)(tid>>5)*N + nbase + n4*4;
    int lane = tid & 31, gp = lane >> 2, t4 = lane & 3;
    int w = tid >> 5, mb = (w & 3)*32, nb = (w >> 2)*64;

    float acc[2][8][4];
#pragma unroll
    for (int a = 0; a < 2; a++)
#pragma unroll
        for (int b = 0; b < 8; b++)
#pragma unroll
            for (int c = 0; c < 4; c++) acc[a][b][c] = 0.f;

    float4 va[4], vb[4];
#pragma unroll
    for (int i = 0; i < 4; i++) {
        va[i] = *(const float4*)aP[i];
        vb[i] = *(const float4*)(bP + (size_t)(8*i)*N);
    }
    int nkt = K >> 5;

    auto stage = [&](float* base) {
        float* Ah = base; float* Bh = base + BM*LDA;
        float* Al = Bh + 32*LDB; float* Bl = Al + BM*LDA;
#pragma unroll
        for (int i = 0; i < 4; i++) {
            int m = (tid >> 3) + 32*i;
            float vv[4] = {va[i].x, va[i].y, va[i].z, va[i].w};
            float4 hi, lo; float* hp = &hi.x; float* lp = &lo.x;
#pragma unroll
            for (int j = 0; j < 4; j++) {
                unsigned h2 = f2tf(vv[j]);
                hp[j] = __uint_as_float(h2);
                lp[j] = __uint_as_float(f2tf(vv[j] - __uint_as_float(h2)));
            }
            *(float4*)(Ah + m*LDA + k4*4) = hi;
            *(float4*)(Al + m*LDA + k4*4) = lo;
            int kr = (tid >> 5) + 8*i;
            float bv[4] = {vb[i].x, vb[i].y, vb[i].z, vb[i].w};
#pragma unroll
            for (int j = 0; j < 4; j++) {
                unsigned h2 = f2tf(bv[j]);
                hp[j] = __uint_as_float(h2);
                lp[j] = __uint_as_float(f2tf(bv[j] - __uint_as_float(h2)));
            }
            *(float4*)(Bh + kr*LDB + n4*4) = hi;
            *(float4*)(Bl + kr*LDB + n4*4) = lo;
        }
    };
    auto compute = [&](float* base) {
        float* Ah = base; float* Bh = base + BM*LDA;
        float* Al = Bh + 32*LDB; float* Bl = Al + BM*LDA;
#pragma unroll
        for (int ks = 0; ks < 4; ks++) {
            int kf = ks*8 + t4;
            unsigned a[2][4], al[2][4];
#pragma unroll
            for (int mt = 0; mt < 2; mt++) {
                int r = mb + mt*16 + gp;
                a[mt][0] = __float_as_uint(Ah[r*LDA + kf]);
                a[mt][1] = __float_as_uint(Ah[(r+8)*LDA + kf]);
                a[mt][2] = __float_as_uint(Ah[r*LDA + kf + 4]);
                a[mt][3] = __float_as_uint(Ah[(r+8)*LDA + kf + 4]);
                al[mt][0] = __float_as_uint(Al[r*LDA + kf]);
                al[mt][1] = __float_as_uint(Al[(r+8)*LDA + kf]);
                al[mt][2] = __float_as_uint(Al[r*LDA + kf + 4]);
                al[mt][3] = __float_as_uint(Al[(r+8)*LDA + kf + 4]);
            }
#pragma unroll
            for (int nt = 0; nt < 8; nt++) {
                int c = nb + nt*8 + gp;
                unsigned b0 = __float_as_uint(Bh[kf*LDB + c]);
                unsigned b1 = __float_as_uint(Bh[(kf+4)*LDB + c]);
                unsigned c0 = __float_as_uint(Bl[kf*LDB + c]);
                unsigned c1 = __float_as_uint(Bl[(kf+4)*LDB + c]);
#pragma unroll
                for (int mt = 0; mt < 2; mt++) {
                    mma_tf32(acc[mt][nt], a[mt], b0, b1);
                    mma_tf32(acc[mt][nt], a[mt], c0, c1);
                    mma_tf32(acc[mt][nt], al[mt], b0, b1);
                }
            }
        }
    };

    stage(sm);
    __syncthreads();
    for (int kt = 0; kt < nkt; kt++) {
        if (kt + 1 < nkt) {
#pragma unroll
            for (int i = 0; i < 4; i++) {
                va[i] = *(const float4*)(aP[i] + (kt+1)*32);
                vb[i] = *(const float4*)(bP + (size_t)((kt+1)*32 + 8*i)*N);
            }
        }
        compute(sm + (kt & 1)*SS);
        if (kt + 1 < nkt) stage(sm + ((kt+1) & 1)*SS);
        __syncthreads();
    }
#pragma unroll
    for (int mt = 0; mt < 2; mt++) {
        int r0 = rowbase + mb + mt*16 + gp;
        int r1 = r0 + 8;
#pragma unroll
        for (int nt = 0; nt < 8; nt++) {
            int col = nbase + nb + nt*8 + t4*2;
            float2 v0 = make_float2(acc[mt][nt][0], acc[mt][nt][1]);
            float2 v1 = make_float2(acc[mt][nt][2], acc[mt][nt][3]);
            if (EPI == 1) {
                float2 x0 = *(const float2*)(X + (size_t)r0*ldc + col);
                float2 x1 = *(const float2*)(X + (size_t)r1*ldc + col);
                v0.x += x0.x; v0.y += x0.y; v1.x += x1.x; v1.y += x1.y;
            }
            *(float2*)(C + (size_t)r0*ldc + col) = v0;
            *(float2*)(C + (size_t)r1*ldc + col) = v1;
        }
    }
}

template<int EPI>
__global__ void __launch_bounds__(256) gemm_plain(
    const float* __restrict__ A, const float* __restrict__ B,
    float* __restrict__ C, const float* __restrict__ X, int N, int K, int M)
{
    gemm_core<EPI>(A, B, C, X, N, K, N, M, blockIdx.x, blockIdx.y);
}

// fused wq|wk|wv|wg: bx 0-7 wq, 8-9 wk, 10-11 wv, 12-19 wg
__global__ void __launch_bounds__(256) proj_gemm(
    const float* __restrict__ wq, const float* __restrict__ wk,
    const float* __restrict__ wv, const float* __restrict__ wg)
{
    int bx = blockIdx.x;
    const float* Bp; float* C; int N; int lbx;
    if (bx < 8)       { Bp = wq; C = g_q;    N = 1024; lbx = bx; }
    else if (bx < 10) { Bp = wk; C = g_k;    N = 256;  lbx = bx - 8; }
    else if (bx < 12) { Bp = wv; C = g_v;    N = 256;  lbx = bx - 10; }
    else              { Bp = wg; C = g_gate; N = 1024; lbx = bx - 12; }
    gemm_core<0>(g_xn, Bp, C, nullptr, N, 1024, N, NTOK, lbx, blockIdx.y);
}

// ======= bf16 m16n8k16 MMA GEMM (MoE, post-routing) =======
// BT: bf16 [N][K]. EPI: 0 plain, 3 C=X[row]*acc
template<int EPI>
__device__ __forceinline__ void gemm_bf(
    const float* __restrict__ A, const __nv_bfloat16* __restrict__ BT,
    float* __restrict__ C, const float* __restrict__ X,
    int N, int K, int ldc, const int* __restrict__ off_e,
    const int* __restrict__ rowmap, int bx, int by)
{
    __shared__ unsigned smw[2*PLANE_BF];
    int rowstart = off_e[0], rowend = off_e[1];
    int rowbase = rowstart + by*BM;
    if (rowbase >= rowend) return;
    int tid = threadIdx.x;
    int nbase = bx*BN;
    int m = tid >> 1, half = tid & 1;
    int grow = rowbase + m;
    bool valid = grow < rowend;
    int ar = valid ? (rowmap ? rowmap[grow] : grow)
                   : (rowmap ? rowmap[rowstart] : rowstart);
    const float* aRow = A + (size_t)ar*K + half*16;
    const __nv_bfloat16* bRow = BT + (size_t)(nbase + m)*K + half*16;

    int lane = tid & 31, gp = lane >> 2, t4 = lane & 3;
    int w = tid >> 5, mb = (w & 3)*32, nb = (w >> 2)*64;
    float acc[2][8][4];
#pragma unroll
    for (int a = 0; a < 2; a++)
#pragma unroll
        for (int b = 0; b < 8; b++)
#pragma unroll
            for (int c = 0; c < 4; c++) acc[a][b][c] = 0.f;

    float4 va[4]; uint4 vb0, vb1;
#pragma unroll
    for (int j = 0; j < 4; j++)
        va[j] = valid ? *(const float4*)(aRow + j*4) : make_float4(0,0,0,0);
    vb0 = *(const uint4*)bRow;
    vb1 = *(const uint4*)(bRow + 8);
    int nkt = K >> 5;

    auto stage = [&](unsigned* s) {
        unsigned* Arow = s + m*PITCH + half*8;
        uint4 p0, p1;
        p0.x = pack_bf(va[0].x, va[0].y); p0.y = pack_bf(va[0].z, va[0].w);
        p0.z = pack_bf(va[1].x, va[1].y); p0.w = pack_bf(va[1].z, va[1].w);
        p1.x = pack_bf(va[2].x, va[2].y); p1.y = pack_bf(va[2].z, va[2].w);
        p1.z = pack_bf(va[3].x, va[3].y); p1.w = pack_bf(va[3].z, va[3].w);
        *(uint4*)Arow = p0; *(uint4*)(Arow + 4) = p1;
        unsigned* Brow = s + 128*PITCH + m*PITCH + half*8;
        *(uint4*)Brow = vb0; *(uint4*)(Brow + 4) = vb1;
    };
    auto compute = [&](unsigned* s) {
        unsigned* Bs = s + 128*PITCH;
#pragma unroll
        for (int ks = 0; ks < 2; ks++) {
            int kb = ks*8;
            unsigned a[2][4];
#pragma unroll
            for (int mt = 0; mt < 2; mt++) {
                int base = (mb + mt*16 + gp)*PITCH + kb + t4;
                a[mt][0] = s[base];
                a[mt][1] = s[base + 8*PITCH];
                a[mt][2] = s[base + 4];
                a[mt][3] = s[base + 8*PITCH + 4];
            }
#pragma unroll
            for (int nt = 0; nt < 8; nt++) {
                int bbase = (nb + nt*8 + gp)*PITCH + kb + t4;
                unsigned b0 = Bs[bbase], b1 = Bs[bbase + 4];
                mma_bf16(acc[0][nt], a[0], b0, b1);
                mma_bf16(acc[1][nt], a[1], b0, b1);
            }
        }
    };

    stage(smw);
    __syncthreads();
    for (int kt = 0; kt < nkt; kt++) {
        if (kt + 1 < nkt) {
#pragma unroll
            for (int j = 0; j < 4; j++)
                va[j] = valid ? *(const float4*)(aRow + (kt+1)*32 + j*4) : make_float4(0,0,0,0);
            vb0 = *(const uint4*)(bRow + (kt+1)*32);
            vb1 = *(const uint4*)(bRow + (kt+1)*32 + 8);
        }
        compute(smw + (kt & 1)*PLANE_BF);
        if (kt + 1 < nkt) stage(smw + ((kt+1) & 1)*PLANE_BF);
        __syncthreads();
    }
#pragma unroll
    for (int mt = 0; mt < 2; mt++) {
        int r0 = rowbase + mb + mt*16 + gp;
        int r1 = r0 + 8;
        float s0 = 0.f, s1 = 0.f;
        if (EPI == 3) {
            s0 = (r0 < rowend) ? X[r0] : 0.f;
            s1 = (r1 < rowend) ? X[r1] : 0.f;
        }
#pragma unroll
        for (int nt = 0; nt < 8; nt++) {
            int col = nbase + nb + nt*8 + t4*2;
            if (r0 < rowend) {
                float2 v = make_float2(acc[mt][nt][0], acc[mt][nt][1]);
                if (EPI == 3) { v.x *= s0; v.y *= s0; }
                *(float2*)(C + (size_t)r0*ldc + col) = v;
            }
            if (r1 < rowend) {
                float2 v = make_float2(acc[mt][nt][2], acc[mt][nt][3]);
                if (EPI == 3) { v.x *= s1; v.y *= s1; }
                *(float2*)(C + (size_t)r1*ldc + col) = v;
            }
        }
    }
}

__global__ void __launch_bounds__(256) moe13_gemm() {
    int z = blockIdx.z, e = z >> 1;
    const __nv_bfloat16* BT = ((z & 1) ? g_w3T : g_w1T) + (size_t)e*FF_*D_;
    float* C = (z & 1) ? g_h3 : g_h;
    gemm_bf<0>(g_xn2, BT, C, nullptr, FF_, D_, FF_, g_off + e, g_permTok,
               blockIdx.x, blockIdx.y);
}
__global__ void __launch_bounds__(256) moe2_gemm() {
    int e = blockIdx.z;
    gemm_bf<3>(g_h, g_w2T + (size_t)e*D_*FF_, g_tmp, g_permW, D_, FF_, D_,
               g_off + e, nullptr, blockIdx.x, blockIdx.y);
}

// ======= weight transpose+convert: src[e][R][C] f32 -> dst[e][C][R] bf16 =======
__global__ void transpose_bf(const float* __restrict__ src, __nv_bfloat16* __restrict__ dst,
                             int R, int C) {
    __shared__ float t[32][33];
    int e = blockIdx.z;
    src += (size_t)e*R*C; dst += (size_t)e*R*C;
    int c0 = blockIdx.x*32, r0 = blockIdx.y*32;
    int lx = threadIdx.x & 31, ly = threadIdx.x >> 5;
#pragma unroll
    for (int i = 0; i < 32; i += 8)
        t[ly+i][lx] = src[(size_t)(r0+ly+i)*C + c0+lx];
    __syncthreads();
#pragma unroll
    for (int i = 0; i < 32; i += 8)
        dst[(size_t)(c0+ly+i)*R + r0+lx] = __float2bfloat16(t[lx][ly+i]);
}

// ======= rmsnorm =======
__global__ void rmsnorm_kernel(const float* __restrict__ x, const float* __restrict__ w,
                               float* __restrict__ out, float eps) {
    int t = blockIdx.x;
    const float4* xr = (const float4*)(x + (size_t)t * D_);
    float4 v = xr[threadIdx.x];
    float ss = v.x*v.x + v.y*v.y + v.z*v.z + v.w*v.w;
    __shared__ float smr[8];
    for (int o = 16; o > 0; o >>= 1) ss += __shfl_xor_sync(0xffffffffu, ss, o);
    if ((threadIdx.x & 31) == 0) smr[threadIdx.x >> 5] = ss;
    __syncthreads();
    if (threadIdx.x < 8) {
        float s2 = smr[threadIdx.x];
        for (int o = 4; o > 0; o >>= 1) s2 += __shfl_xor_sync(0xffu, s2, o);
        if (threadIdx.x == 0) smr[0] = s2;
    }
    __syncthreads();
    float sc = rsqrtf(smr[0] * (1.0f / D_) + eps);
    float4 wv = ((const float4*)w)[threadIdx.x];
    ((float4*)(out + (size_t)t * D_))[threadIdx.x] =
        make_float4(v.x*sc*wv.x, v.y*sc*wv.y, v.z*sc*wv.z, v.w*sc*wv.w);
}

// ======= q/k rmsnorm + rope =======
__global__ void qkrope_kernel(float* buf, const float* __restrict__ w, int nheads) {
    int wid = (blockIdx.x * blockDim.x + threadIdx.x) >> 5;
    int lane = threadIdx.x & 31;
    int t = wid / nheads, h = wid - t * nheads;
    int pos = t & (S_ - 1);
    size_t base = (size_t)t * nheads * HD_ + h * HD_;
    float v0 = buf[base + 2*lane], v1 = buf[base + 2*lane + 1];
    float ss = v0*v0 + v1*v1;
    for (int o = 16; o > 0; o >>= 1) ss += __shfl_xor_sync(0xffffffffu, ss, o);
    float sc = rsqrtf(ss * (1.0f / HD_) + 1e-5f);
    float a  = v0 * sc * w[2*lane];
    float b2 = v1 * sc * w[2*lane + 1];
    float inv = expf(-(float)lane * (2.0f / HD_) * 9.210340371976184f);
    float ang = (float)pos * inv;
    float cs = cosf(ang), sn = sinf(ang);
    buf[base + 2*lane]     = a*cs - b2*sn;
    buf[base + 2*lane + 1] = a*sn + b2*cs;
}

// ======= flash attention (fp32 SIMT, BQ=128 BK=64) =======
__global__ void __launch_bounds__(256) attn_v2(
    const float* __restrict__ Q, const float* __restrict__ Kb,
    const float* __restrict__ Vb, float* __restrict__ O)
{
    extern __shared__ float smA[];
    float* QsT = smA;
    float* KsT = QsT + 64*132;
    float* Vs  = KsT + 64*68;
    float* Ps  = Vs  + 64*68;
    int qt = blockIdx.x, h = blockIdx.y, b = blockIdx.z;
    int kh = h >> 2;
    int tid = threadIdx.x;
    int ty = tid >> 4, tx = tid & 15;

#pragma unroll
    for (int i = 0; i < 8; i++) {
        int id = tid + i*256;
        int q = id >> 4, d4 = id & 15;
        float4 v = *(const float4*)(Q + ((size_t)(b*S_ + qt*128 + q))*(H_*HD_) + h*HD_ + d4*4);
        QsT[(d4*4+0)*132 + q] = v.x * 0.125f;
        QsT[(d4*4+1)*132 + q] = v.y * 0.125f;
        QsT[(d4*4+2)*132 + q] = v.z * 0.125f;
        QsT[(d4*4+3)*132 + q] = v.w * 0.125f;
    }
    float m[8], l[8], o[8][4];
#pragma unroll
    for (int i = 0; i < 8; i++) {
        m[i] = NEG_BIG; l[i] = 0.f;
#pragma unroll
        for (int j = 0; j < 4; j++) o[i][j] = 0.f;
    }
    int nkt = 2*(qt+1);
    for (int kt = 0; kt < nkt; kt++) {
        __syncthreads();
#pragma unroll
        for (int i = 0; i < 4; i++) {
            int id = tid + i*256;
            int k = id >> 4, d4 = id & 15;
            size_t gb = ((size_t)(b*S_ + kt*64 + k))*(KH_*HD_) + kh*HD_ + d4*4;
            float4 kv = *(const float4*)(Kb + gb);
            KsT[(d4*4+0)*68 + k] = kv.x;
            KsT[(d4*4+1)*68 + k] = kv.y;
            KsT[(d4*4+2)*68 + k] = kv.z;
            KsT[(d4*4+3)*68 + k] = kv.w;
            *(float4*)&Vs[k*68 + d4*4] = *(const float4*)(Vb + gb);
        }
        __syncthreads();
        float s[8][4];
#pragma unroll
        for (int i = 0; i < 8; i++)
#pragma unroll
            for (int j = 0; j < 4; j++) s[i][j] = 0.f;
#pragma unroll 4
        for (int d = 0; d < 64; d++) {
            float4 q0 = *(float4*)&QsT[d*132 + ty*8];
            float4 q1 = *(float4*)&QsT[d*132 + ty*8 + 4];
            float4 kk = *(float4*)&KsT[d*68 + tx*4];
            float qa[8] = {q0.x,q0.y,q0.z,q0.w,q1.x,q1.y,q1.z,q1.w};
            float kb2[4] = {kk.x,kk.y,kk.z,kk.w};
#pragma unroll
            for (int i = 0; i < 8; i++)
#pragma unroll
                for (int j = 0; j < 4; j++) s[i][j] += qa[i]*kb2[j];
        }
        int qg0 = qt*128 + ty*8;
        int kg0 = kt*64 + tx*4;
#pragma unroll
        for (int i = 0; i < 8; i++)
#pragma unroll
            for (int j = 0; j < 4; j++)
                if (kg0 + j > qg0 + i) s[i][j] = NEG_BIG;
#pragma unroll
        for (int i = 0; i < 8; i++) {
            float mx = fmaxf(fmaxf(s[i][0], s[i][1]), fmaxf(s[i][2], s[i][3]));
            mx = fmaxf(mx, __shfl_xor_sync(0xffffffffu, mx, 1));
            mx = fmaxf(mx, __shfl_xor_sync(0xffffffffu, mx, 2));
            mx = fmaxf(mx, __shfl_xor_sync(0xffffffffu, mx, 4));
            mx = fmaxf(mx, __shfl_xor_sync(0xffffffffu, mx, 8));
            float mn = fmaxf(m[i], mx);
            float al = __expf(m[i] - mn);
            float ls = 0.f;
#pragma unroll
            for (int j = 0; j < 4; j++) {
                float e = __expf(s[i][j] - mn);
                s[i][j] = e; ls += e;
            }
            ls += __shfl_xor_sync(0xffffffffu, ls, 1);
            ls += __shfl_xor_sync(0xffffffffu, ls, 2);
            ls += __shfl_xor_sync(0xffffffffu, ls, 4);
            ls += __shfl_xor_sync(0xffffffffu, ls, 8);
            l[i] = l[i]*al + ls; m[i] = mn;
#pragma unroll
            for (int j = 0; j < 4; j++) o[i][j] *= al;
        }
#pragma unroll
        for (int i = 0; i < 8; i++)
            *(float4*)&Ps[(ty*8+i)*68 + tx*4] = make_float4(s[i][0], s[i][1], s[i][2], s[i][3]);
        __syncthreads();
#pragma unroll 2
        for (int k4 = 0; k4 < 16; k4++) {
            float4 vv0 = *(float4*)&Vs[(k4*4+0)*68 + tx*4];
            float4 vv1 = *(float4*)&Vs[(k4*4+1)*68 + tx*4];
            float4 vv2 = *(float4*)&Vs[(k4*4+2)*68 + tx*4];
            float4 vv3 = *(float4*)&Vs[(k4*4+3)*68 + tx*4];
#pragma unroll
            for (int i = 0; i < 8; i++) {
                float4 p = *(float4*)&Ps[(ty*8+i)*68 + k4*4];
                o[i][0] += p.x*vv0.x + p.y*vv1.x + p.z*vv2.x + p.w*vv3.x;
                o[i][1] += p.x*vv0.y + p.y*vv1.y + p.z*vv2.y + p.w*vv3.y;
                o[i][2] += p.x*vv0.z + p.y*vv1.z + p.z*vv2.z + p.w*vv3.z;
                o[i][3] += p.x*vv0.w + p.y*vv1.w + p.z*vv2.w + p.w*vv3.w;
            }
        }
    }
#pragma unroll
    for (int i = 0; i < 8; i++) {
        float inv = 1.f / l[i];
        size_t ob = ((size_t)(b*S_ + qt*128 + ty*8 + i))*(H_*HD_) + h*HD_ + tx*4;
        *(float4*)(O + ob) = make_float4(o[i][0]*inv, o[i][1]*inv, o[i][2]*inv, o[i][3]*inv);
    }
}

// ======= elementwise =======
__global__ void gatemul_kernel() {
    size_t i = (size_t)blockIdx.x * 256 + threadIdx.x;
    float4 g = ((float4*)g_gate)[i];
    float4 a = ((float4*)g_attn)[i];
    g.x = a.x / (1.f + __expf(-g.x));
    g.y = a.y / (1.f + __expf(-g.y));
    g.z = a.z / (1.f + __expf(-g.z));
    g.w = a.w / (1.f + __expf(-g.w));
    ((float4*)g_gate)[i] = g;
}
__global__ void silumul_kernel() {
    size_t i = (size_t)blockIdx.x * 256 + threadIdx.x;
    float4 a = ((float4*)g_h)[i];
    float4 b = ((float4*)g_h3)[i];
    a.x = a.x / (1.f + __expf(-a.x)) * b.x;
    a.y = a.y / (1.f + __expf(-a.y)) * b.y;
    a.z = a.z / (1.f + __expf(-a.z)) * b.z;
    a.w = a.w / (1.f + __expf(-a.w)) * b.w;
    ((float4*)g_h)[i] = a;
}

// ======= router + moe bookkeeping =======
__global__ void router_kernel(const float* __restrict__ rw) {
    int t = blockIdx.x;
    const float* x = g_xn2 + (size_t)t * D_;
    float le[8] = {0,0,0,0,0,0,0,0};
    for (int d = threadIdx.x; d < D_; d += 256) {
        float xv = x[d];
        const float4* r4 = (const float4*)(rw + (size_t)d * 8);
        float4 aa = r4[0], bb = r4[1];
        le[0] += xv*aa.x; le[1] += xv*aa.y; le[2] += xv*aa.z; le[3] += xv*aa.w;
        le[4] += xv*bb.x; le[5] += xv*bb.y; le[6] += xv*bb.z; le[7] += xv*bb.w;
    }
#pragma unroll
    for (int e = 0; e < 8; e++)
        for (int o = 16; o > 0; o >>= 1)
            le[e] += __shfl_xor_sync(0xffffffffu, le[e], o);
    __shared__ float smr[8][8];
    if ((threadIdx.x & 31) == 0)
#pragma unroll
        for (int e = 0; e < 8; e++) smr[threadIdx.x >> 5][e] = le[e];
    __syncthreads();
    if (threadIdx.x == 0) {
        float lg[8];
#pragma unroll
        for (int e = 0; e < 8; e++) {
            float s = 0.f;
            for (int w2 = 0; w2 < 8; w2++) s += smr[w2][e];
            lg[e] = s;
        }
        float mx = lg[0];
        for (int e = 1; e < 8; e++) mx = fmaxf(mx, lg[e]);
        float p[8], s = 0.f;
        for (int e = 0; e < 8; e++) { p[e] = expf(lg[e] - mx); s += p[e]; }
        float invs = 1.f / s;
        for (int e = 0; e < 8; e++) { p[e] *= invs; atomicAdd(&g_probsum[e], p[e]); }
        int i0 = 0;
        for (int e = 1; e < 8; e++) if (p[e] > p[i0]) i0 = e;
        int i1 = (i0 == 0) ? 1 : 0;
        for (int e = 0; e < 8; e++) if (e != i0 && p[e] > p[i1]) i1 = e;
        float tv0 = p[i0], tv1 = p[i1], s2 = tv0 + tv1;
        g_topi[t*2] = i0; g_topi[t*2+1] = i1;
        g_topv[t*2] = tv0/s2; g_topv[t*2+1] = tv1/s2;
        atomicAdd(&g_counts[i0], 1);
        atomicAdd(&g_counts[i1], 1);
    }
}
__global__ void zero_kernel() {
    int t = threadIdx.x;
    if (t < E_) { g_counts[t] = 0; g_cursor[t] = 0; g_probsum[t] = 0.f; }
}
__global__ void offsets_aux_kernel(float* __restrict__ aux_out) {
    if (threadIdx.x == 0) {
        int o = 0;
        for (int e = 0; e < E_; e++) { g_off[e] = o; o += g_counts[e]; }
        g_off[E_] = o;
        float aux = 0.f;
        for (int e = 0; e < E_; e++)
            aux += ((float)g_counts[e] / (NTOK*2.0f)) * (g_probsum[e] / (float)NTOK);
        aux_out[0] = 0.01f * (float)E_ * aux;
    }
}
__global__ void scatter_kernel() {
    int t = blockIdx.x * 256 + threadIdx.x;
    if (t >= NTOK) return;
#pragma unroll
    for (int k2 = 0; k2 < 2; k2++) {
        int e = g_topi[t*2+k2];
        int pos = g_off[e] + atomicAdd(&g_cursor[e], 1);
        g_permTok[pos] = t;
        g_permW[pos] = g_topv[t*2+k2];
        g_tokSlot[t*2+k2] = pos;
    }
}
__global__ void finaladd_kernel(float* __restrict__ out) {
    size_t i = (size_t)blockIdx.x * 256 + threadIdx.x;
    int t = (int)(i >> 10);
    int d = (int)(i & 1023);
    int s0 = g_tokSlot[t*2], s1 = g_tokSlot[t*2+1];
    out[i] = g_x1[i] + g_tmp[(size_t)s0*D_ + d] + g_tmp[(size_t)s1*D_ + d];
}

// ======= host launcher =======
extern "C" void kernel_launch(void* const* d_in, const int* in_sizes, int n_in,
                              void* d_out, int out_size) {
    const float* x        = (const float*)d_in[0];
    const float* attn_nw  = (const float*)d_in[1];
    const float* ffn_nw   = (const float*)d_in[2];
    const float* q_nw     = (const float*)d_in[3];
    const float* k_nw     = (const float*)d_in[4];
    const float* wq       = (const float*)d_in[5];
    const float* wk       = (const float*)d_in[6];
    const float* wv       = (const float*)d_in[7];
    const float* wo       = (const float*)d_in[8];
    const float* wg       = (const float*)d_in[9];
    const float* router_w = (const float*)d_in[10];
    const float* w1       = (const float*)d_in[11];
    const float* w3       = (const float*)d_in[12];
    const float* w2       = (const float*)d_in[13];
    float* out = (float*)d_out;

    float *p_xn, *p_q, *p_k, *p_v, *p_gate, *p_x1, *p_xn2, *p_attn;
    __nv_bfloat16 *p_w1T, *p_w3T, *p_w2T;
    cudaGetSymbolAddress((void**)&p_xn, g_xn);
    cudaGetSymbolAddress((void**)&p_q, g_q);
    cudaGetSymbolAddress((void**)&p_k, g_k);
    cudaGetSymbolAddress((void**)&p_v, g_v);
    cudaGetSymbolAddress((void**)&p_gate, g_gate);
    cudaGetSymbolAddress((void**)&p_attn, g_attn);
    cudaGetSymbolAddress((void**)&p_x1, g_x1);
    cudaGetSymbolAddress((void**)&p_xn2, g_xn2);
    cudaGetSymbolAddress((void**)&p_w1T, g_w1T);
    cudaGetSymbolAddress((void**)&p_w3T, g_w3T);
    cudaGetSymbolAddress((void**)&p_w2T, g_w2T);

    cudaFuncSetAttribute(proj_gemm, cudaFuncAttributeMaxDynamicSharedMemorySize, SMEM_GEMM_S);
    cudaFuncSetAttribute(gemm_plain<1>, cudaFuncAttributeMaxDynamicSharedMemorySize, SMEM_GEMM_S);
    cudaFuncSetAttribute(attn_v2, cudaFuncAttributeMaxDynamicSharedMemorySize, SMEM_ATTN);

    // weight convert+transpose (overlaps conceptually with attn path being independent)
    transpose_bf<<<dim3(FF_/32, D_/32, E_), 256>>>(w1, p_w1T, D_, FF_);
    transpose_bf<<<dim3(FF_/32, D_/32, E_), 256>>>(w3, p_w3T, D_, FF_);
    transpose_bf<<<dim3(D_/32, FF_/32, E_), 256>>>(w2, p_w2T, FF_, D_);

    rmsnorm_kernel<<<NTOK, 256>>>(x, attn_nw, p_xn, 1e-6f);
    proj_gemm<<<dim3(20,32), 256, SMEM_GEMM_S>>>(wq, wk, wv, wg);
    qkrope_kernel<<<(NTOK*H_*32)/256, 256>>>(p_q, q_nw, H_);
    qkrope_kernel<<<(NTOK*KH_*32)/256, 256>>>(p_k, k_nw, KH_);
    attn_v2<<<dim3(S_/128, H_, B_), 256, SMEM_ATTN>>>(p_q, p_k, p_v, p_attn);
    gatemul_kernel<<<(NTOK*1024/4)/256, 256>>>();
    gemm_plain<1><<<dim3(8,32), 256, SMEM_GEMM_S>>>(p_gate, wo, p_x1, x, 1024, 1024, NTOK);
    rmsnorm_kernel<<<NTOK, 256>>>(p_x1, ffn_nw, p_xn2, 1e-6f);
    zero_kernel<<<1, 32>>>();
    router_kernel<<<NTOK, 256>>>(router_w);
    offsets_aux_kernel<<<1, 32>>>(out + (size_t)NTOK*D_);
    scatter_kernel<<<NTOK/256, 256>>>();
    moe13_gemm<<<dim3(FF_/128, 32, 16), 256>>>();
    silumul_kernel<<<((size_t)NSLOT*FF_/4)/256, 256>>>();
    moe2_gemm<<<dim3(D_/128, 32, 8), 256>>>();
    finaladd_kernel<<<(NTOK*1024)/256, 256>>>(out);
}

// round 6
// speedup vs baseline: 6.0225x; 1.0301x over previous
#include <cuda_runtime.h>
#include <math.h>
#include <stdint.h>

#define B_ 2
#define S_ 2048
#define D_ 1024
#define H_ 16
#define KH_ 4
#define HD_ 64
#define E_ 8
#define FF_ 2048
#define NTOK (B_*S_)
#define NSLOT (NTOK*2)
#define NEG_BIG -3.0e38f

#define BM 128
#define BN 128
#define LDA 36
#define LDB 136
#define PLANE (BM*LDA + 32*LDB)
#define SMEM_GEMM   (2*PLANE*4)
#define SMEM_GEMM_S (4*PLANE*4)
// attn smem: Qh,Ql[128][68], Kh,Kl[64][68], Vs[64][68], Ps[128][68], m/l/alph[128]
#define SMEM_ATTN2 ((2*128*68 + 3*64*68 + 128*68 + 3*128)*4)

__device__ float g_xn  [NTOK*D_];
__device__ float g_q   [NTOK*H_*HD_];
__device__ float g_k   [NTOK*KH_*HD_];
__device__ float g_v   [NTOK*KH_*HD_];
__device__ float g_gate[NTOK*H_*HD_];
__device__ float g_attn[NTOK*H_*HD_];
__device__ float g_x1  [NTOK*D_];
__device__ float g_xn2 [NTOK*D_];
__device__ float g_h   [(size_t)NSLOT*FF_];
__device__ float g_h3  [(size_t)NSLOT*FF_];
__device__ float g_tmp [(size_t)NSLOT*D_];
__device__ int   g_topi[NTOK*2];
__device__ float g_topv[NTOK*2];
__device__ int   g_permTok[NSLOT];
__device__ float g_permW  [NSLOT];
__device__ int   g_tokSlot[NTOK*2];
__device__ int   g_counts[E_];
__device__ int   g_off   [E_+1];
__device__ int   g_cursor[E_];
__device__ float g_probsum[E_];

__device__ __forceinline__ unsigned f2tf(float v) {
    unsigned r; asm("cvt.rna.tf32.f32 %0, %1;" : "=r"(r) : "f"(v)); return r;
}
__device__ __forceinline__ void mma_tf32(float* d, const unsigned* a, unsigned b0, unsigned b1) {
    asm volatile("mma.sync.aligned.m16n8k8.row.col.f32.tf32.tf32.f32 "
        "{%0,%1,%2,%3}, {%4,%5,%6,%7}, {%8,%9}, {%0,%1,%2,%3};"
        : "+f"(d[0]), "+f"(d[1]), "+f"(d[2]), "+f"(d[3])
        : "r"(a[0]), "r"(a[1]), "r"(a[2]), "r"(a[3]), "r"(b0), "r"(b1));
}

// ======= tf32 MMA GEMM 128x128x32, double-buffered. EPI: 0 plain, 1 +X, 3 X[row]* =======
template<int EPI, bool SPLIT>
__device__ __forceinline__ void gemm_core(
    const float* __restrict__ A, const float* __restrict__ B,
    float* __restrict__ C, const float* __restrict__ X,
    int N, int K, int ldc, int rowstart, int rowend,
    const int* __restrict__ rowmap, int bx, int by)
{
    extern __shared__ float sm[];
    const int SS = PLANE * (SPLIT ? 2 : 1);
    int tid = threadIdx.x;
    int rowbase = rowstart + by*BM;
    if (rowbase >= rowend) return;
    int nbase = bx*BN;
    int k4 = tid & 7, n4 = tid & 31;
    const float* aP[4]; bool av[4];
#pragma unroll
    for (int i = 0; i < 4; i++) {
        int grow = rowbase + (tid >> 3) + 32*i;
        av[i] = grow < rowend;
        int ar = av[i] ? (rowmap ? rowmap[grow] : grow)
                       : (rowmap ? rowmap[rowstart] : rowstart);
        aP[i] = A + (size_t)ar*K + k4*4;
    }
    const float* bP = B + (size_t)(tid>>5)*N + nbase + n4*4;
    int lane = tid & 31, gp = lane >> 2, t4 = lane & 3;
    int w = tid >> 5, mb = (w & 3)*32, nb = (w >> 2)*64;

    float acc[2][8][4];
#pragma unroll
    for (int a = 0; a < 2; a++)
#pragma unroll
        for (int b = 0; b < 8; b++)
#pragma unroll
            for (int c = 0; c < 4; c++) acc[a][b][c] = 0.f;

    float4 va[4], vb[4];
#pragma unroll
    for (int i = 0; i < 4; i++) {
        va[i] = av[i] ? *(const float4*)aP[i] : make_float4(0,0,0,0);
        vb[i] = *(const float4*)(bP + (size_t)(8*i)*N);
    }
    int nkt = K >> 5;

    auto stage = [&](float* base) {
        float* Ah = base; float* Bh = base + BM*LDA;
        float* Al = Bh + 32*LDB; float* Bl = Al + BM*LDA;
#pragma unroll
        for (int i = 0; i < 4; i++) {
            int m = (tid >> 3) + 32*i;
            float vv[4] = {va[i].x, va[i].y, va[i].z, va[i].w};
            float4 hi, lo; float* hp = &hi.x; float* lp = &lo.x;
#pragma unroll
            for (int j = 0; j < 4; j++) {
                unsigned h2 = f2tf(vv[j]);
                hp[j] = __uint_as_float(h2);
                if (SPLIT) lp[j] = __uint_as_float(f2tf(vv[j] - __uint_as_float(h2)));
            }
            *(float4*)(Ah + m*LDA + k4*4) = hi;
            if (SPLIT) *(float4*)(Al + m*LDA + k4*4) = lo;
            int kr = (tid >> 5) + 8*i;
            float bv[4] = {vb[i].x, vb[i].y, vb[i].z, vb[i].w};
#pragma unroll
            for (int j = 0; j < 4; j++) {
                unsigned h2 = f2tf(bv[j]);
                hp[j] = __uint_as_float(h2);
                if (SPLIT) lp[j] = __uint_as_float(f2tf(bv[j] - __uint_as_float(h2)));
            }
            *(float4*)(Bh + kr*LDB + n4*4) = hi;
            if (SPLIT) *(float4*)(Bl + kr*LDB + n4*4) = lo;
        }
    };
    auto compute = [&](float* base) {
        float* Ah = base; float* Bh = base + BM*LDA;
        float* Al = Bh + 32*LDB; float* Bl = Al + BM*LDA;
#pragma unroll
        for (int ks = 0; ks < 4; ks++) {
            int kf = ks*8 + t4;
            unsigned a[2][4], al[2][4];
#pragma unroll
            for (int mt = 0; mt < 2; mt++) {
                int r = mb + mt*16 + gp;
                a[mt][0] = __float_as_uint(Ah[r*LDA + kf]);
                a[mt][1] = __float_as_uint(Ah[(r+8)*LDA + kf]);
                a[mt][2] = __float_as_uint(Ah[r*LDA + kf + 4]);
                a[mt][3] = __float_as_uint(Ah[(r+8)*LDA + kf + 4]);
                if (SPLIT) {
                    al[mt][0] = __float_as_uint(Al[r*LDA + kf]);
                    al[mt][1] = __float_as_uint(Al[(r+8)*LDA + kf]);
                    al[mt][2] = __float_as_uint(Al[r*LDA + kf + 4]);
                    al[mt][3] = __float_as_uint(Al[(r+8)*LDA + kf + 4]);
                }
            }
#pragma unroll
            for (int nt = 0; nt < 8; nt++) {
                int c = nb + nt*8 + gp;
                unsigned b0 = __float_as_uint(Bh[kf*LDB + c]);
                unsigned b1 = __float_as_uint(Bh[(kf+4)*LDB + c]);
#pragma unroll
                for (int mt = 0; mt < 2; mt++) mma_tf32(acc[mt][nt], a[mt], b0, b1);
                if (SPLIT) {
                    unsigned c0 = __float_as_uint(Bl[kf*LDB + c]);
                    unsigned c1 = __float_as_uint(Bl[(kf+4)*LDB + c]);
#pragma unroll
                    for (int mt = 0; mt < 2; mt++) {
                        mma_tf32(acc[mt][nt], a[mt], c0, c1);
                        mma_tf32(acc[mt][nt], al[mt], b0, b1);
                    }
                }
            }
        }
    };

    stage(sm);
    __syncthreads();
    for (int kt = 0; kt < nkt; kt++) {
        if (kt + 1 < nkt) {
#pragma unroll
            for (int i = 0; i < 4; i++) {
                va[i] = av[i] ? *(const float4*)(aP[i] + (kt+1)*32) : make_float4(0,0,0,0);
                vb[i] = *(const float4*)(bP + (size_t)((kt+1)*32 + 8*i)*N);
            }
        }
        compute(sm + (kt & 1)*SS);
        if (kt + 1 < nkt) stage(sm + ((kt+1) & 1)*SS);
        __syncthreads();
    }
#pragma unroll
    for (int mt = 0; mt < 2; mt++) {
        int r0 = rowbase + mb + mt*16 + gp;
        int r1 = r0 + 8;
        float s0 = 0.f, s1 = 0.f;
        if (EPI == 3) {
            s0 = (r0 < rowend) ? X[r0] : 0.f;
            s1 = (r1 < rowend) ? X[r1] : 0.f;
        }
#pragma unroll
        for (int nt = 0; nt < 8; nt++) {
            int col = nbase + nb + nt*8 + t4*2;
            if (r0 < rowend) {
                float2 v = make_float2(acc[mt][nt][0], acc[mt][nt][1]);
                if (EPI == 1) { float2 xr = *(const float2*)(X + (size_t)r0*ldc + col); v.x += xr.x; v.y += xr.y; }
                if (EPI == 3) { v.x *= s0; v.y *= s0; }
                *(float2*)(C + (size_t)r0*ldc + col) = v;
            }
            if (r1 < rowend) {
                float2 v = make_float2(acc[mt][nt][2], acc[mt][nt][3]);
                if (EPI == 1) { float2 xr = *(const float2*)(X + (size_t)r1*ldc + col); v.x += xr.x; v.y += xr.y; }
                if (EPI == 3) { v.x *= s1; v.y *= s1; }
                *(float2*)(C + (size_t)r1*ldc + col) = v;
            }
        }
    }
}

template<int EPI, bool SPLIT>
__global__ void __launch_bounds__(256) gemm_plain(
    const float* __restrict__ A, const float* __restrict__ B,
    float* __restrict__ C, const float* __restrict__ X, int N, int K, int M)
{
    gemm_core<EPI,SPLIT>(A, B, C, X, N, K, N, 0, M, nullptr, blockIdx.x, blockIdx.y);
}

__global__ void __launch_bounds__(256) proj_gemm(
    const float* __restrict__ wq, const float* __restrict__ wk,
    const float* __restrict__ wv, const float* __restrict__ wg)
{
    int bx = blockIdx.x;
    const float* Bp; float* C; int N; int lbx;
    if (bx < 8)       { Bp = wq; C = g_q;    N = 1024; lbx = bx; }
    else if (bx < 10) { Bp = wk; C = g_k;    N = 256;  lbx = bx - 8; }
    else if (bx < 12) { Bp = wv; C = g_v;    N = 256;  lbx = bx - 10; }
    else              { Bp = wg; C = g_gate; N = 1024; lbx = bx - 12; }
    gemm_core<0,true>(g_xn, Bp, C, nullptr, N, 1024, N, 0, NTOK, nullptr, lbx, blockIdx.y);
}

__global__ void __launch_bounds__(256) moe13_gemm(
    const float* __restrict__ w1, const float* __restrict__ w3)
{
    int z = blockIdx.z, e = z >> 1;
    const float* B = ((z & 1) ? w3 : w1) + (size_t)e*D_*FF_;
    float* C = (z & 1) ? g_h3 : g_h;
    gemm_core<0,false>(g_xn2, B, C, nullptr, FF_, D_, FF_,
                       g_off[e], g_off[e+1], g_permTok, blockIdx.x, blockIdx.y);
}
__global__ void __launch_bounds__(256) moe2_gemm(const float* __restrict__ w2)
{
    int e = blockIdx.z;
    gemm_core<3,false>(g_h, w2 + (size_t)e*FF_*D_, g_tmp, g_permW, D_, FF_, D_,
                       g_off[e], g_off[e+1], nullptr, blockIdx.x, blockIdx.y);
}

// ======= rmsnorm =======
__global__ void rmsnorm_kernel(const float* __restrict__ x, const float* __restrict__ w,
                               float* __restrict__ out, float eps) {
    int t = blockIdx.x;
    const float4* xr = (const float4*)(x + (size_t)t * D_);
    float4 v = xr[threadIdx.x];
    float ss = v.x*v.x + v.y*v.y + v.z*v.z + v.w*v.w;
    __shared__ float smr[8];
    for (int o = 16; o > 0; o >>= 1) ss += __shfl_xor_sync(0xffffffffu, ss, o);
    if ((threadIdx.x & 31) == 0) smr[threadIdx.x >> 5] = ss;
    __syncthreads();
    if (threadIdx.x < 8) {
        float s2 = smr[threadIdx.x];
        for (int o = 4; o > 0; o >>= 1) s2 += __shfl_xor_sync(0xffu, s2, o);
        if (threadIdx.x == 0) smr[0] = s2;
    }
    __syncthreads();
    float sc = rsqrtf(smr[0] * (1.0f / D_) + eps);
    float4 wv = ((const float4*)w)[threadIdx.x];
    ((float4*)(out + (size_t)t * D_))[threadIdx.x] =
        make_float4(v.x*sc*wv.x, v.y*sc*wv.y, v.z*sc*wv.z, v.w*sc*wv.w);
}

// ======= q/k rmsnorm + rope =======
__global__ void qkrope_kernel(float* buf, const float* __restrict__ w, int nheads) {
    int wid = (blockIdx.x * blockDim.x + threadIdx.x) >> 5;
    int lane = threadIdx.x & 31;
    int t = wid / nheads, h = wid - t * nheads;
    int pos = t & (S_ - 1);
    size_t base = (size_t)t * nheads * HD_ + h * HD_;
    float v0 = buf[base + 2*lane], v1 = buf[base + 2*lane + 1];
    float ss = v0*v0 + v1*v1;
    for (int o = 16; o > 0; o >>= 1) ss += __shfl_xor_sync(0xffffffffu, ss, o);
    float sc = rsqrtf(ss * (1.0f / HD_) + 1e-5f);
    float a  = v0 * sc * w[2*lane];
    float b2 = v1 * sc * w[2*lane + 1];
    float inv = expf(-(float)lane * (2.0f / HD_) * 9.210340371976184f);
    float ang = (float)pos * inv;
    float cs = cosf(ang), sn = sinf(ang);
    buf[base + 2*lane]     = a*cs - b2*sn;
    buf[base + 2*lane + 1] = a*sn + b2*cs;
}

// ======= attention: split-tf32 MMA QK^T + fragment softmax + SIMT PV =======
__global__ void __launch_bounds__(256) attn_tc(
    const float* __restrict__ Q, const float* __restrict__ Kb,
    const float* __restrict__ Vb, float* __restrict__ O)
{
    extern __shared__ float sma[];
    float* Qh = sma;                  // [128][68]
    float* Ql = Qh + 128*68;          // [128][68]
    float* Kh = Ql + 128*68;          // [64][68]
    float* Kl = Kh + 64*68;           // [64][68]
    float* Vs = Kl + 64*68;           // [64][68]
    float* Ps = Vs + 64*68;           // [128][68]
    float* m_arr = Ps + 128*68;       // [128]
    float* l_arr = m_arr + 128;       // [128]
    float* alph  = l_arr + 128;       // [128]
    int qt = blockIdx.x, h = blockIdx.y, b = blockIdx.z;
    int kh = h >> 2;
    int tid = threadIdx.x;
    int w = tid >> 5, lane = tid & 31, gp = lane >> 2, t4 = lane & 3;
    int ty = tid >> 4, tx = tid & 15;          // PV mapping

    // stage Q (scaled by 1/8), split hi/lo
#pragma unroll
    for (int i = 0; i < 8; i++) {
        int id = tid + i*256;
        int q = id >> 4, d4 = id & 15;
        float4 v = *(const float4*)(Q + ((size_t)(b*S_ + qt*128 + q))*(H_*HD_) + h*HD_ + d4*4);
        float vv[4] = {v.x*0.125f, v.y*0.125f, v.z*0.125f, v.w*0.125f};
        float4 hi, lo; float* hp = &hi.x; float* lp = &lo.x;
#pragma unroll
        for (int j = 0; j < 4; j++) {
            unsigned hb = f2tf(vv[j]);
            hp[j] = __uint_as_float(hb);
            lp[j] = __uint_as_float(f2tf(vv[j] - __uint_as_float(hb)));
        }
        *(float4*)(Qh + q*68 + d4*4) = hi;
        *(float4*)(Ql + q*68 + d4*4) = lo;
    }
    if (tid < 128) { m_arr[tid] = NEG_BIG; l_arr[tid] = 0.f; }

    float o[8][4];
#pragma unroll
    for (int i = 0; i < 8; i++)
#pragma unroll
        for (int j = 0; j < 4; j++) o[i][j] = 0.f;
    int nkt = 2*(qt + 1);

    for (int kt = 0; kt < nkt; kt++) {
        __syncthreads();
        // load K (split) + V
#pragma unroll
        for (int i = 0; i < 4; i++) {
            int id = tid + i*256;
            int k = id >> 4, d4 = id & 15;
            size_t gb = ((size_t)(b*S_ + kt*64 + k))*(KH_*HD_) + kh*HD_ + d4*4;
            float4 kv = *(const float4*)(Kb + gb);
            float vv[4] = {kv.x, kv.y, kv.z, kv.w};
            float4 hi, lo; float* hp = &hi.x; float* lp = &lo.x;
#pragma unroll
            for (int j = 0; j < 4; j++) {
                unsigned hb = f2tf(vv[j]);
                hp[j] = __uint_as_float(hb);
                lp[j] = __uint_as_float(f2tf(vv[j] - __uint_as_float(hb)));
            }
            *(float4*)(Kh + k*68 + d4*4) = hi;
            *(float4*)(Kl + k*68 + d4*4) = lo;
            *(float4*)(Vs + k*68 + d4*4) = *(const float4*)(Vb + gb);
        }
        __syncthreads();

        // MMA: S[w*16+..16][64] = Q*K^T (split-tf32)
        float s[8][4];
#pragma unroll
        for (int nt = 0; nt < 8; nt++)
#pragma unroll
            for (int j = 0; j < 4; j++) s[nt][j] = 0.f;
#pragma unroll
        for (int kb = 0; kb < 8; kb++) {
            int arow = (w*16 + gp)*68 + kb*8 + t4;
            unsigned ah[4], al2[4];
            ah[0] = __float_as_uint(Qh[arow]);
            ah[1] = __float_as_uint(Qh[arow + 8*68]);
            ah[2] = __float_as_uint(Qh[arow + 4]);
            ah[3] = __float_as_uint(Qh[arow + 8*68 + 4]);
            al2[0] = __float_as_uint(Ql[arow]);
            al2[1] = __float_as_uint(Ql[arow + 8*68]);
            al2[2] = __float_as_uint(Ql[arow + 4]);
            al2[3] = __float_as_uint(Ql[arow + 8*68 + 4]);
#pragma unroll
            for (int nt = 0; nt < 8; nt++) {
                int baddr = (nt*8 + gp)*68 + kb*8 + t4;
                unsigned bh0 = __float_as_uint(Kh[baddr]);
                unsigned bh1 = __float_as_uint(Kh[baddr + 4]);
                unsigned bl0 = __float_as_uint(Kl[baddr]);
                unsigned bl1 = __float_as_uint(Kl[baddr + 4]);
                mma_tf32(s[nt], ah, bh0, bh1);
                mma_tf32(s[nt], ah, bl0, bl1);
                mma_tf32(s[nt], al2, bh0, bh1);
            }
        }

        // mask + online softmax on fragments
        int qrow0 = qt*128 + w*16 + gp;
        int qrow1 = qrow0 + 8;
        int colb = kt*64;
#pragma unroll
        for (int nt = 0; nt < 8; nt++) {
            int c0 = colb + nt*8 + t4*2;
            if (c0     > qrow0) s[nt][0] = NEG_BIG;
            if (c0 + 1 > qrow0) s[nt][1] = NEG_BIG;
            if (c0     > qrow1) s[nt][2] = NEG_BIG;
            if (c0 + 1 > qrow1) s[nt][3] = NEG_BIG;
        }
        float mx0 = NEG_BIG, mx1 = NEG_BIG;
#pragma unroll
        for (int nt = 0; nt < 8; nt++) {
            mx0 = fmaxf(mx0, fmaxf(s[nt][0], s[nt][1]));
            mx1 = fmaxf(mx1, fmaxf(s[nt][2], s[nt][3]));
        }
        mx0 = fmaxf(mx0, __shfl_xor_sync(0xffffffffu, mx0, 1));
        mx0 = fmaxf(mx0, __shfl_xor_sync(0xffffffffu, mx0, 2));
        mx1 = fmaxf(mx1, __shfl_xor_sync(0xffffffffu, mx1, 1));
        mx1 = fmaxf(mx1, __shfl_xor_sync(0xffffffffu, mx1, 2));
        int lr0 = w*16 + gp, lr1 = lr0 + 8;
        float mo0 = m_arr[lr0], mo1 = m_arr[lr1];
        float mn0 = fmaxf(mo0, mx0), mn1 = fmaxf(mo1, mx1);
        float al0 = __expf(mo0 - mn0), al1 = __expf(mo1 - mn1);
        float ls0 = 0.f, ls1 = 0.f;
#pragma unroll
        for (int nt = 0; nt < 8; nt++) {
            float e0 = __expf(s[nt][0] - mn0); s[nt][0] = e0; ls0 += e0;
            float e1 = __expf(s[nt][1] - mn0); s[nt][1] = e1; ls0 += e1;
            float e2 = __expf(s[nt][2] - mn1); s[nt][2] = e2; ls1 += e2;
            float e3 = __expf(s[nt][3] - mn1); s[nt][3] = e3; ls1 += e3;
        }
        ls0 += __shfl_xor_sync(0xffffffffu, ls0, 1);
        ls0 += __shfl_xor_sync(0xffffffffu, ls0, 2);
        ls1 += __shfl_xor_sync(0xffffffffu, ls1, 1);
        ls1 += __shfl_xor_sync(0xffffffffu, ls1, 2);
        if (t4 == 0) {
            m_arr[lr0] = mn0; l_arr[lr0] = l_arr[lr0]*al0 + ls0; alph[lr0] = al0;
            m_arr[lr1] = mn1; l_arr[lr1] = l_arr[lr1]*al1 + ls1; alph[lr1] = al1;
        }
#pragma unroll
        for (int nt = 0; nt < 8; nt++) {
            *(float2*)(Ps + lr0*68 + nt*8 + t4*2) = make_float2(s[nt][0], s[nt][1]);
            *(float2*)(Ps + lr1*68 + nt*8 + t4*2) = make_float2(s[nt][2], s[nt][3]);
        }
        __syncthreads();

        // SIMT PV
        float alr[8];
#pragma unroll
        for (int i = 0; i < 8; i++) alr[i] = alph[ty*8 + i];
#pragma unroll
        for (int i = 0; i < 8; i++)
#pragma unroll
            for (int j = 0; j < 4; j++) o[i][j] *= alr[i];
#pragma unroll 2
        for (int k4 = 0; k4 < 16; k4++) {
            float4 vv0 = *(float4*)&Vs[(k4*4+0)*68 + tx*4];
            float4 vv1 = *(float4*)&Vs[(k4*4+1)*68 + tx*4];
            float4 vv2 = *(float4*)&Vs[(k4*4+2)*68 + tx*4];
            float4 vv3 = *(float4*)&Vs[(k4*4+3)*68 + tx*4];
#pragma unroll
            for (int i = 0; i < 8; i++) {
                float4 p = *(float4*)&Ps[(ty*8+i)*68 + k4*4];
                o[i][0] += p.x*vv0.x + p.y*vv1.x + p.z*vv2.x + p.w*vv3.x;
                o[i][1] += p.x*vv0.y + p.y*vv1.y + p.z*vv2.y + p.w*vv3.y;
                o[i][2] += p.x*vv0.z + p.y*vv1.z + p.z*vv2.z + p.w*vv3.z;
                o[i][3] += p.x*vv0.w + p.y*vv1.w + p.z*vv2.w + p.w*vv3.w;
            }
        }
    }
#pragma unroll
    for (int i = 0; i < 8; i++) {
        float inv = 1.f / l_arr[ty*8 + i];
        size_t ob = ((size_t)(b*S_ + qt*128 + ty*8 + i))*(H_*HD_) + h*HD_ + tx*4;
        *(float4*)(O + ob) = make_float4(o[i][0]*inv, o[i][1]*inv, o[i][2]*inv, o[i][3]*inv);
    }
}

// ======= elementwise =======
__global__ void gatemul_kernel() {
    size_t i = (size_t)blockIdx.x * 256 + threadIdx.x;
    float4 g = ((float4*)g_gate)[i];
    float4 a = ((float4*)g_attn)[i];
    g.x = a.x / (1.f + __expf(-g.x));
    g.y = a.y / (1.f + __expf(-g.y));
    g.z = a.z / (1.f + __expf(-g.z));
    g.w = a.w / (1.f + __expf(-g.w));
    ((float4*)g_gate)[i] = g;
}
__global__ void silumul_kernel() {
    size_t i = (size_t)blockIdx.x * 256 + threadIdx.x;
    float4 a = ((float4*)g_h)[i];
    float4 b = ((float4*)g_h3)[i];
    a.x = a.x / (1.f + __expf(-a.x)) * b.x;
    a.y = a.y / (1.f + __expf(-a.y)) * b.y;
    a.z = a.z / (1.f + __expf(-a.z)) * b.z;
    a.w = a.w / (1.f + __expf(-a.w)) * b.w;
    ((float4*)g_h)[i] = a;
}

// ======= router + moe bookkeeping =======
__global__ void router_kernel(const float* __restrict__ rw) {
    int t = blockIdx.x;
    const float* x = g_xn2 + (size_t)t * D_;
    float le[8] = {0,0,0,0,0,0,0,0};
    for (int d = threadIdx.x; d < D_; d += 256) {
        float xv = x[d];
        const float4* r4 = (const float4*)(rw + (size_t)d * 8);
        float4 aa = r4[0], bb = r4[1];
        le[0] += xv*aa.x; le[1] += xv*aa.y; le[2] += xv*aa.z; le[3] += xv*aa.w;
        le[4] += xv*bb.x; le[5] += xv*bb.y; le[6] += xv*bb.z; le[7] += xv*bb.w;
    }
#pragma unroll
    for (int e = 0; e < 8; e++)
        for (int o = 16; o > 0; o >>= 1)
            le[e] += __shfl_xor_sync(0xffffffffu, le[e], o);
    __shared__ float smr[8][8];
    if ((threadIdx.x & 31) == 0)
#pragma unroll
        for (int e = 0; e < 8; e++) smr[threadIdx.x >> 5][e] = le[e];
    __syncthreads();
    if (threadIdx.x == 0) {
        float lg[8];
#pragma unroll
        for (int e = 0; e < 8; e++) {
            float s = 0.f;
            for (int w2 = 0; w2 < 8; w2++) s += smr[w2][e];
            lg[e] = s;
        }
        float mx = lg[0];
        for (int e = 1; e < 8; e++) mx = fmaxf(mx, lg[e]);
        float p[8], s = 0.f;
        for (int e = 0; e < 8; e++) { p[e] = expf(lg[e] - mx); s += p[e]; }
        float invs = 1.f / s;
        for (int e = 0; e < 8; e++) { p[e] *= invs; atomicAdd(&g_probsum[e], p[e]); }
        int i0 = 0;
        for (int e = 1; e < 8; e++) if (p[e] > p[i0]) i0 = e;
        int i1 = (i0 == 0) ? 1 : 0;
        for (int e = 0; e < 8; e++) if (e != i0 && p[e] > p[i1]) i1 = e;
        float tv0 = p[i0], tv1 = p[i1], s2 = tv0 + tv1;
        g_topi[t*2] = i0; g_topi[t*2+1] = i1;
        g_topv[t*2] = tv0/s2; g_topv[t*2+1] = tv1/s2;
        atomicAdd(&g_counts[i0], 1);
        atomicAdd(&g_counts[i1], 1);
    }
}
__global__ void zero_kernel() {
    int t = threadIdx.x;
    if (t < E_) { g_counts[t] = 0; g_cursor[t] = 0; g_probsum[t] = 0.f; }
}
__global__ void offsets_aux_kernel(float* __restrict__ aux_out) {
    if (threadIdx.x == 0) {
        int o = 0;
        for (int e = 0; e < E_; e++) { g_off[e] = o; o += g_counts[e]; }
        g_off[E_] = o;
        float aux = 0.f;
        for (int e = 0; e < E_; e++)
            aux += ((float)g_counts[e] / (NTOK*2.0f)) * (g_probsum[e] / (float)NTOK);
        aux_out[0] = 0.01f * (float)E_ * aux;
    }
}
__global__ void scatter_kernel() {
    int t = blockIdx.x * 256 + threadIdx.x;
    if (t >= NTOK) return;
#pragma unroll
    for (int k2 = 0; k2 < 2; k2++) {
        int e = g_topi[t*2+k2];
        int pos = g_off[e] + atomicAdd(&g_cursor[e], 1);
        g_permTok[pos] = t;
        g_permW[pos] = g_topv[t*2+k2];
        g_tokSlot[t*2+k2] = pos;
    }
}
__global__ void finaladd_kernel(float* __restrict__ out) {
    size_t i = (size_t)blockIdx.x * 256 + threadIdx.x;
    int t = (int)(i >> 10);
    int d = (int)(i & 1023);
    int s0 = g_tokSlot[t*2], s1 = g_tokSlot[t*2+1];
    out[i] = g_x1[i] + g_tmp[(size_t)s0*D_ + d] + g_tmp[(size_t)s1*D_ + d];
}

// ======= host launcher =======
extern "C" void kernel_launch(void* const* d_in, const int* in_sizes, int n_in,
                              void* d_out, int out_size) {
    const float* x        = (const float*)d_in[0];
    const float* attn_nw  = (const float*)d_in[1];
    const float* ffn_nw   = (const float*)d_in[2];
    const float* q_nw     = (const float*)d_in[3];
    const float* k_nw     = (const float*)d_in[4];
    const float* wq       = (const float*)d_in[5];
    const float* wk       = (const float*)d_in[6];
    const float* wv       = (const float*)d_in[7];
    const float* wo       = (const float*)d_in[8];
    const float* wg       = (const float*)d_in[9];
    const float* router_w = (const float*)d_in[10];
    const float* w1       = (const float*)d_in[11];
    const float* w3       = (const float*)d_in[12];
    const float* w2       = (const float*)d_in[13];
    float* out = (float*)d_out;

    float *p_xn, *p_q, *p_k, *p_v, *p_gate, *p_x1, *p_xn2, *p_attn;
    cudaGetSymbolAddress((void**)&p_xn, g_xn);
    cudaGetSymbolAddress((void**)&p_q, g_q);
    cudaGetSymbolAddress((void**)&p_k, g_k);
    cudaGetSymbolAddress((void**)&p_v, g_v);
    cudaGetSymbolAddress((void**)&p_gate, g_gate);
    cudaGetSymbolAddress((void**)&p_attn, g_attn);
    cudaGetSymbolAddress((void**)&p_x1, g_x1);
    cudaGetSymbolAddress((void**)&p_xn2, g_xn2);

    cudaFuncSetAttribute(proj_gemm, cudaFuncAttributeMaxDynamicSharedMemorySize, SMEM_GEMM_S);
    cudaFuncSetAttribute(gemm_plain<1,true>, cudaFuncAttributeMaxDynamicSharedMemorySize, SMEM_GEMM_S);
    cudaFuncSetAttribute(moe13_gemm, cudaFuncAttributeMaxDynamicSharedMemorySize, SMEM_GEMM);
    cudaFuncSetAttribute(moe2_gemm, cudaFuncAttributeMaxDynamicSharedMemorySize, SMEM_GEMM);
    cudaFuncSetAttribute(attn_tc, cudaFuncAttributeMaxDynamicSharedMemorySize, SMEM_ATTN2);

    rmsnorm_kernel<<<NTOK, 256>>>(x, attn_nw, p_xn, 1e-6f);
    proj_gemm<<<dim3(20,32), 256, SMEM_GEMM_S>>>(wq, wk, wv, wg);
    qkrope_kernel<<<(NTOK*H_*32)/256, 256>>>(p_q, q_nw, H_);
    qkrope_kernel<<<(NTOK*KH_*32)/256, 256>>>(p_k, k_nw, KH_);
    attn_tc<<<dim3(S_/128, H_, B_), 256, SMEM_ATTN2>>>(p_q, p_k, p_v, p_attn);
    gatemul_kernel<<<(NTOK*1024/4)/256, 256>>>();
    gemm_plain<1,true><<<dim3(8,32), 256, SMEM_GEMM_S>>>(p_gate, wo, p_x1, x, 1024, 1024, NTOK);
    rmsnorm_kernel<<<NTOK, 256>>>(p_x1, ffn_nw, p_xn2, 1e-6f);
    zero_kernel<<<1, 32>>>();
    router_kernel<<<NTOK, 256>>>(router_w);
    offsets_aux_kernel<<<1, 32>>>(out + (size_t)NTOK*D_);
    scatter_kernel<<<NTOK/256, 256>>>();
    moe13_gemm<<<dim3(FF_/128, 32, 16), 256, SMEM_GEMM>>>(w1, w3);
    silumul_kernel<<<((size_t)NSLOT*FF_/4)/256, 256>>>();
    moe2_gemm<<<dim3(D_/128, 32, 8), 256, SMEM_GEMM>>>(w2);
    finaladd_kernel<<<(NTOK*1024)/256, 256>>>(out);
}

// round 7
// speedup vs baseline: 6.4239x; 1.0666x over previous
#include <cuda_runtime.h>
#include <math.h>
#include <stdint.h>

#define B_ 2
#define S_ 2048
#define D_ 1024
#define H_ 16
#define KH_ 4
#define HD_ 64
#define E_ 8
#define FF_ 2048
#define NTOK (B_*S_)
#define NSLOT (NTOK*2)
#define NEG_BIG -3.0e38f

#define BM 128
#define BN 128
#define LDA 36
#define LDB 136
#define PLANE (BM*LDA + 32*LDB)
#define SMEM_GEMM   (2*PLANE*4)
#define SMEM_GEMM_S (4*PLANE*4)
// attn smem: Qh,Ql[128][68], Kh,Kl[64][68], Vh,Vl[64][72], Ph,Pl[128][68]
#define SMEM_ATTN3 ((2*128*68 + 2*64*68 + 2*64*72 + 2*128*68)*4)

__device__ float g_xn  [NTOK*D_];
__device__ float g_q   [NTOK*H_*HD_];
__device__ float g_k   [NTOK*KH_*HD_];
__device__ float g_v   [NTOK*KH_*HD_];
__device__ float g_gate[NTOK*H_*HD_];
__device__ float g_attn[NTOK*H_*HD_];
__device__ float g_x1  [NTOK*D_];
__device__ float g_xn2 [NTOK*D_];
__device__ float g_h   [(size_t)NSLOT*FF_];
__device__ float g_h3  [(size_t)NSLOT*FF_];
__device__ float g_tmp [(size_t)NSLOT*D_];
__device__ int   g_topi[NTOK*2];
__device__ float g_topv[NTOK*2];
__device__ int   g_permTok[NSLOT];
__device__ float g_permW  [NSLOT];
__device__ int   g_tokSlot[NTOK*2];
__device__ int   g_counts[E_];
__device__ int   g_off   [E_+1];
__device__ int   g_cursor[E_];
__device__ float g_probsum[E_];

__device__ __forceinline__ unsigned f2tf(float v) {
    unsigned r; asm("cvt.rna.tf32.f32 %0, %1;" : "=r"(r) : "f"(v)); return r;
}
__device__ __forceinline__ void mma_tf32(float* d, const unsigned* a, unsigned b0, unsigned b1) {
    asm volatile("mma.sync.aligned.m16n8k8.row.col.f32.tf32.tf32.f32 "
        "{%0,%1,%2,%3}, {%4,%5,%6,%7}, {%8,%9}, {%0,%1,%2,%3};"
        : "+f"(d[0]), "+f"(d[1]), "+f"(d[2]), "+f"(d[3])
        : "r"(a[0]), "r"(a[1]), "r"(a[2]), "r"(a[3]), "r"(b0), "r"(b1));
}

// ======= tf32 MMA GEMM 128x128x32, double-buffered. EPI: 0 plain, 1 +X, 3 X[row]* =======
template<int EPI, bool SPLIT>
__device__ __forceinline__ void gemm_core(
    const float* __restrict__ A, const float* __restrict__ B,
    float* __restrict__ C, const float* __restrict__ X,
    int N, int K, int ldc, int rowstart, int rowend,
    const int* __restrict__ rowmap, int bx, int by)
{
    extern __shared__ float sm[];
    const int SS = PLANE * (SPLIT ? 2 : 1);
    int tid = threadIdx.x;
    int rowbase = rowstart + by*BM;
    if (rowbase >= rowend) return;
    int nbase = bx*BN;
    int k4 = tid & 7, n4 = tid & 31;
    const float* aP[4]; bool av[4];
#pragma unroll
    for (int i = 0; i < 4; i++) {
        int grow = rowbase + (tid >> 3) + 32*i;
        av[i] = grow < rowend;
        int ar = av[i] ? (rowmap ? rowmap[grow] : grow)
                       : (rowmap ? rowmap[rowstart] : rowstart);
        aP[i] = A + (size_t)ar*K + k4*4;
    }
    const float* bP = B + (size_t)(tid>>5)*N + nbase + n4*4;
    int lane = tid & 31, gp = lane >> 2, t4 = lane & 3;
    int w = tid >> 5, mb = (w & 3)*32, nb = (w >> 2)*64;

    float acc[2][8][4];
#pragma unroll
    for (int a = 0; a < 2; a++)
#pragma unroll
        for (int b = 0; b < 8; b++)
#pragma unroll
            for (int c = 0; c < 4; c++) acc[a][b][c] = 0.f;

    float4 va[4], vb[4];
#pragma unroll
    for (int i = 0; i < 4; i++) {
        va[i] = av[i] ? *(const float4*)aP[i] : make_float4(0,0,0,0);
        vb[i] = *(const float4*)(bP + (size_t)(8*i)*N);
    }
    int nkt = K >> 5;

    auto stage = [&](float* base) {
        float* Ah = base; float* Bh = base + BM*LDA;
        float* Al = Bh + 32*LDB; float* Bl = Al + BM*LDA;
#pragma unroll
        for (int i = 0; i < 4; i++) {
            int m = (tid >> 3) + 32*i;
            float vv[4] = {va[i].x, va[i].y, va[i].z, va[i].w};
            float4 hi, lo; float* hp = &hi.x; float* lp = &lo.x;
#pragma unroll
            for (int j = 0; j < 4; j++) {
                unsigned h2 = f2tf(vv[j]);
                hp[j] = __uint_as_float(h2);
                if (SPLIT) lp[j] = __uint_as_float(f2tf(vv[j] - __uint_as_float(h2)));
            }
            *(float4*)(Ah + m*LDA + k4*4) = hi;
            if (SPLIT) *(float4*)(Al + m*LDA + k4*4) = lo;
            int kr = (tid >> 5) + 8*i;
            float bv[4] = {vb[i].x, vb[i].y, vb[i].z, vb[i].w};
#pragma unroll
            for (int j = 0; j < 4; j++) {
                unsigned h2 = f2tf(bv[j]);
                hp[j] = __uint_as_float(h2);
                if (SPLIT) lp[j] = __uint_as_float(f2tf(bv[j] - __uint_as_float(h2)));
            }
            *(float4*)(Bh + kr*LDB + n4*4) = hi;
            if (SPLIT) *(float4*)(Bl + kr*LDB + n4*4) = lo;
        }
    };
    auto compute = [&](float* base) {
        float* Ah = base; float* Bh = base + BM*LDA;
        float* Al = Bh + 32*LDB; float* Bl = Al + BM*LDA;
#pragma unroll
        for (int ks = 0; ks < 4; ks++) {
            int kf = ks*8 + t4;
            unsigned a[2][4], al[2][4];
#pragma unroll
            for (int mt = 0; mt < 2; mt++) {
                int r = mb + mt*16 + gp;
                a[mt][0] = __float_as_uint(Ah[r*LDA + kf]);
                a[mt][1] = __float_as_uint(Ah[(r+8)*LDA + kf]);
                a[mt][2] = __float_as_uint(Ah[r*LDA + kf + 4]);
                a[mt][3] = __float_as_uint(Ah[(r+8)*LDA + kf + 4]);
                if (SPLIT) {
                    al[mt][0] = __float_as_uint(Al[r*LDA + kf]);
                    al[mt][1] = __float_as_uint(Al[(r+8)*LDA + kf]);
                    al[mt][2] = __float_as_uint(Al[r*LDA + kf + 4]);
                    al[mt][3] = __float_as_uint(Al[(r+8)*LDA + kf + 4]);
                }
            }
#pragma unroll
            for (int nt = 0; nt < 8; nt++) {
                int c = nb + nt*8 + gp;
                unsigned b0 = __float_as_uint(Bh[kf*LDB + c]);
                unsigned b1 = __float_as_uint(Bh[(kf+4)*LDB + c]);
#pragma unroll
                for (int mt = 0; mt < 2; mt++) mma_tf32(acc[mt][nt], a[mt], b0, b1);
                if (SPLIT) {
                    unsigned c0 = __float_as_uint(Bl[kf*LDB + c]);
                    unsigned c1 = __float_as_uint(Bl[(kf+4)*LDB + c]);
#pragma unroll
                    for (int mt = 0; mt < 2; mt++) {
                        mma_tf32(acc[mt][nt], a[mt], c0, c1);
                        mma_tf32(acc[mt][nt], al[mt], b0, b1);
                    }
                }
            }
        }
    };

    stage(sm);
    __syncthreads();
    for (int kt = 0; kt < nkt; kt++) {
        if (kt + 1 < nkt) {
#pragma unroll
            for (int i = 0; i < 4; i++) {
                va[i] = av[i] ? *(const float4*)(aP[i] + (kt+1)*32) : make_float4(0,0,0,0);
                vb[i] = *(const float4*)(bP + (size_t)((kt+1)*32 + 8*i)*N);
            }
        }
        compute(sm + (kt & 1)*SS);
        if (kt + 1 < nkt) stage(sm + ((kt+1) & 1)*SS);
        __syncthreads();
    }
#pragma unroll
    for (int mt = 0; mt < 2; mt++) {
        int r0 = rowbase + mb + mt*16 + gp;
        int r1 = r0 + 8;
        float s0 = 0.f, s1 = 0.f;
        if (EPI == 3) {
            s0 = (r0 < rowend) ? X[r0] : 0.f;
            s1 = (r1 < rowend) ? X[r1] : 0.f;
        }
#pragma unroll
        for (int nt = 0; nt < 8; nt++) {
            int col = nbase + nb + nt*8 + t4*2;
            if (r0 < rowend) {
                float2 v = make_float2(acc[mt][nt][0], acc[mt][nt][1]);
                if (EPI == 1) { float2 xr = *(const float2*)(X + (size_t)r0*ldc + col); v.x += xr.x; v.y += xr.y; }
                if (EPI == 3) { v.x *= s0; v.y *= s0; }
                *(float2*)(C + (size_t)r0*ldc + col) = v;
            }
            if (r1 < rowend) {
                float2 v = make_float2(acc[mt][nt][2], acc[mt][nt][3]);
                if (EPI == 1) { float2 xr = *(const float2*)(X + (size_t)r1*ldc + col); v.x += xr.x; v.y += xr.y; }
                if (EPI == 3) { v.x *= s1; v.y *= s1; }
                *(float2*)(C + (size_t)r1*ldc + col) = v;
            }
        }
    }
}

template<int EPI, bool SPLIT>
__global__ void __launch_bounds__(256) gemm_plain(
    const float* __restrict__ A, const float* __restrict__ B,
    float* __restrict__ C, const float* __restrict__ X, int N, int K, int M)
{
    gemm_core<EPI,SPLIT>(A, B, C, X, N, K, N, 0, M, nullptr, blockIdx.x, blockIdx.y);
}

__global__ void __launch_bounds__(256) proj_gemm(
    const float* __restrict__ wq, const float* __restrict__ wk,
    const float* __restrict__ wv, const float* __restrict__ wg)
{
    int bx = blockIdx.x;
    const float* Bp; float* C; int N; int lbx;
    if (bx < 8)       { Bp = wq; C = g_q;    N = 1024; lbx = bx; }
    else if (bx < 10) { Bp = wk; C = g_k;    N = 256;  lbx = bx - 8; }
    else if (bx < 12) { Bp = wv; C = g_v;    N = 256;  lbx = bx - 10; }
    else              { Bp = wg; C = g_gate; N = 1024; lbx = bx - 12; }
    gemm_core<0,true>(g_xn, Bp, C, nullptr, N, 1024, N, 0, NTOK, nullptr, lbx, blockIdx.y);
}

__global__ void __launch_bounds__(256) moe13_gemm(
    const float* __restrict__ w1, const float* __restrict__ w3)
{
    int z = blockIdx.z, e = z >> 1;
    const float* B = ((z & 1) ? w3 : w1) + (size_t)e*D_*FF_;
    float* C = (z & 1) ? g_h3 : g_h;
    gemm_core<0,false>(g_xn2, B, C, nullptr, FF_, D_, FF_,
                       g_off[e], g_off[e+1], g_permTok, blockIdx.x, blockIdx.y);
}
__global__ void __launch_bounds__(256) moe2_gemm(const float* __restrict__ w2)
{
    int e = blockIdx.z;
    gemm_core<3,false>(g_h, w2 + (size_t)e*FF_*D_, g_tmp, g_permW, D_, FF_, D_,
                       g_off[e], g_off[e+1], nullptr, blockIdx.x, blockIdx.y);
}

// ======= rmsnorm =======
__global__ void rmsnorm_kernel(const float* __restrict__ x, const float* __restrict__ w,
                               float* __restrict__ out, float eps) {
    int t = blockIdx.x;
    const float4* xr = (const float4*)(x + (size_t)t * D_);
    float4 v = xr[threadIdx.x];
    float ss = v.x*v.x + v.y*v.y + v.z*v.z + v.w*v.w;
    __shared__ float smr[8];
    for (int o = 16; o > 0; o >>= 1) ss += __shfl_xor_sync(0xffffffffu, ss, o);
    if ((threadIdx.x & 31) == 0) smr[threadIdx.x >> 5] = ss;
    __syncthreads();
    if (threadIdx.x < 8) {
        float s2 = smr[threadIdx.x];
        for (int o = 4; o > 0; o >>= 1) s2 += __shfl_xor_sync(0xffu, s2, o);
        if (threadIdx.x == 0) smr[0] = s2;
    }
    __syncthreads();
    float sc = rsqrtf(smr[0] * (1.0f / D_) + eps);
    float4 wv = ((const float4*)w)[threadIdx.x];
    ((float4*)(out + (size_t)t * D_))[threadIdx.x] =
        make_float4(v.x*sc*wv.x, v.y*sc*wv.y, v.z*sc*wv.z, v.w*sc*wv.w);
}

// ======= q/k rmsnorm + rope =======
__global__ void qkrope_kernel(float* buf, const float* __restrict__ w, int nheads) {
    int wid = (blockIdx.x * blockDim.x + threadIdx.x) >> 5;
    int lane = threadIdx.x & 31;
    int t = wid / nheads, h = wid - t * nheads;
    int pos = t & (S_ - 1);
    size_t base = (size_t)t * nheads * HD_ + h * HD_;
    float v0 = buf[base + 2*lane], v1 = buf[base + 2*lane + 1];
    float ss = v0*v0 + v1*v1;
    for (int o = 16; o > 0; o >>= 1) ss += __shfl_xor_sync(0xffffffffu, ss, o);
    float sc = rsqrtf(ss * (1.0f / HD_) + 1e-5f);
    float a  = v0 * sc * w[2*lane];
    float b2 = v1 * sc * w[2*lane + 1];
    float inv = expf(-(float)lane * (2.0f / HD_) * 9.210340371976184f);
    float ang = (float)pos * inv;
    float cs = cosf(ang), sn = sinf(ang);
    buf[base + 2*lane]     = a*cs - b2*sn;
    buf[base + 2*lane + 1] = a*sn + b2*cs;
}

// ======= attention: split-tf32 MMA for BOTH QK^T and PV, register m/l =======
__global__ void __launch_bounds__(256) attn_tc2(
    const float* __restrict__ Q, const float* __restrict__ Kb,
    const float* __restrict__ Vb, float* __restrict__ O)
{
    extern __shared__ float sma[];
    float* Qh = sma;                  // [128][68]
    float* Ql = Qh + 128*68;
    float* Kh = Ql + 128*68;          // [64][68]
    float* Kl = Kh + 64*68;
    float* Vh = Kl + 64*68;           // [64][72]
    float* Vl = Vh + 64*72;
    float* Ph = Vl + 64*72;           // [128][68]
    float* Pl = Ph + 128*68;
    int qt = blockIdx.x, h = blockIdx.y, b = blockIdx.z;
    int kh = h >> 2;
    int tid = threadIdx.x;
    int w = tid >> 5, lane = tid & 31, gp = lane >> 2, t4 = lane & 3;

    // stage Q (scaled 1/8), split hi/lo
#pragma unroll
    for (int i = 0; i < 8; i++) {
        int id = tid + i*256;
        int q = id >> 4, d4 = id & 15;
        float4 v = *(const float4*)(Q + ((size_t)(b*S_ + qt*128 + q))*(H_*HD_) + h*HD_ + d4*4);
        float vv[4] = {v.x*0.125f, v.y*0.125f, v.z*0.125f, v.w*0.125f};
        float4 hi, lo; float* hp = &hi.x; float* lp = &lo.x;
#pragma unroll
        for (int j = 0; j < 4; j++) {
            unsigned hb = f2tf(vv[j]);
            hp[j] = __uint_as_float(hb);
            lp[j] = __uint_as_float(f2tf(vv[j] - __uint_as_float(hb)));
        }
        *(float4*)(Qh + q*68 + d4*4) = hi;
        *(float4*)(Ql + q*68 + d4*4) = lo;
    }

    float m0 = NEG_BIG, m1 = NEG_BIG, l0 = 0.f, l1 = 0.f;
    float o[8][4];
#pragma unroll
    for (int nt = 0; nt < 8; nt++)
#pragma unroll
        for (int j = 0; j < 4; j++) o[nt][j] = 0.f;
    int nkt = 2*(qt + 1);
    int lr0 = w*16 + gp, lr1 = lr0 + 8;

    for (int kt = 0; kt < nkt; kt++) {
        __syncthreads();
        // stage K split + V split
#pragma unroll
        for (int i = 0; i < 4; i++) {
            int id = tid + i*256;
            int k = id >> 4, d4 = id & 15;
            size_t gb = ((size_t)(b*S_ + kt*64 + k))*(KH_*HD_) + kh*HD_ + d4*4;
            float4 kv = *(const float4*)(Kb + gb);
            float4 vv4 = *(const float4*)(Vb + gb);
            float kk[4] = {kv.x, kv.y, kv.z, kv.w};
            float vvv[4] = {vv4.x, vv4.y, vv4.z, vv4.w};
            float4 khi, klo, vhi, vlo;
            float* khp = &khi.x; float* klp = &klo.x;
            float* vhp = &vhi.x; float* vlp = &vlo.x;
#pragma unroll
            for (int j = 0; j < 4; j++) {
                unsigned hb = f2tf(kk[j]);
                khp[j] = __uint_as_float(hb);
                klp[j] = __uint_as_float(f2tf(kk[j] - __uint_as_float(hb)));
                unsigned vb2 = f2tf(vvv[j]);
                vhp[j] = __uint_as_float(vb2);
                vlp[j] = __uint_as_float(f2tf(vvv[j] - __uint_as_float(vb2)));
            }
            *(float4*)(Kh + k*68 + d4*4) = khi;
            *(float4*)(Kl + k*68 + d4*4) = klo;
            *(float4*)(Vh + k*72 + d4*4) = vhi;
            *(float4*)(Vl + k*72 + d4*4) = vlo;
        }
        __syncthreads();

        // QK^T split-tf32 MMA -> s[nt][4]: rows lr0/lr1, cols nt*8+2t4,+1
        float s[8][4];
#pragma unroll
        for (int nt = 0; nt < 8; nt++)
#pragma unroll
            for (int j = 0; j < 4; j++) s[nt][j] = 0.f;
#pragma unroll
        for (int kb = 0; kb < 8; kb++) {
            int arow = lr0*68 + kb*8 + t4;
            unsigned ah[4], al2[4];
            ah[0] = __float_as_uint(Qh[arow]);
            ah[1] = __float_as_uint(Qh[arow + 8*68]);
            ah[2] = __float_as_uint(Qh[arow + 4]);
            ah[3] = __float_as_uint(Qh[arow + 8*68 + 4]);
            al2[0] = __float_as_uint(Ql[arow]);
            al2[1] = __float_as_uint(Ql[arow + 8*68]);
            al2[2] = __float_as_uint(Ql[arow + 4]);
            al2[3] = __float_as_uint(Ql[arow + 8*68 + 4]);
#pragma unroll
            for (int nt = 0; nt < 8; nt++) {
                int baddr = (nt*8 + gp)*68 + kb*8 + t4;
                unsigned bh0 = __float_as_uint(Kh[baddr]);
                unsigned bh1 = __float_as_uint(Kh[baddr + 4]);
                unsigned bl0 = __float_as_uint(Kl[baddr]);
                unsigned bl1 = __float_as_uint(Kl[baddr + 4]);
                mma_tf32(s[nt], ah, bh0, bh1);
                mma_tf32(s[nt], ah, bl0, bl1);
                mma_tf32(s[nt], al2, bh0, bh1);
            }
        }

        // causal mask + online softmax (register state)
        int qrow0 = qt*128 + lr0;
        int qrow1 = qt*128 + lr1;
        int colb = kt*64;
#pragma unroll
        for (int nt = 0; nt < 8; nt++) {
            int c0 = colb + nt*8 + t4*2;
            if (c0     > qrow0) s[nt][0] = NEG_BIG;
            if (c0 + 1 > qrow0) s[nt][1] = NEG_BIG;
            if (c0     > qrow1) s[nt][2] = NEG_BIG;
            if (c0 + 1 > qrow1) s[nt][3] = NEG_BIG;
        }
        float mx0 = NEG_BIG, mx1 = NEG_BIG;
#pragma unroll
        for (int nt = 0; nt < 8; nt++) {
            mx0 = fmaxf(mx0, fmaxf(s[nt][0], s[nt][1]));
            mx1 = fmaxf(mx1, fmaxf(s[nt][2], s[nt][3]));
        }
        mx0 = fmaxf(mx0, __shfl_xor_sync(0xffffffffu, mx0, 1));
        mx0 = fmaxf(mx0, __shfl_xor_sync(0xffffffffu, mx0, 2));
        mx1 = fmaxf(mx1, __shfl_xor_sync(0xffffffffu, mx1, 1));
        mx1 = fmaxf(mx1, __shfl_xor_sync(0xffffffffu, mx1, 2));
        float mn0 = fmaxf(m0, mx0), mn1 = fmaxf(m1, mx1);
        float al0 = __expf(m0 - mn0), al1 = __expf(m1 - mn1);
        float ls0 = 0.f, ls1 = 0.f;
#pragma unroll
        for (int nt = 0; nt < 8; nt++) {
            float e0 = __expf(s[nt][0] - mn0); s[nt][0] = e0; ls0 += e0;
            float e1 = __expf(s[nt][1] - mn0); s[nt][1] = e1; ls0 += e1;
            float e2 = __expf(s[nt][2] - mn1); s[nt][2] = e2; ls1 += e2;
            float e3 = __expf(s[nt][3] - mn1); s[nt][3] = e3; ls1 += e3;
        }
        ls0 += __shfl_xor_sync(0xffffffffu, ls0, 1);
        ls0 += __shfl_xor_sync(0xffffffffu, ls0, 2);
        ls1 += __shfl_xor_sync(0xffffffffu, ls1, 1);
        ls1 += __shfl_xor_sync(0xffffffffu, ls1, 2);
        l0 = l0*al0 + ls0; m0 = mn0;
        l1 = l1*al1 + ls1; m1 = mn1;

        // write P split to smem; rescale o fragments by alpha
#pragma unroll
        for (int nt = 0; nt < 8; nt++) {
            float p0 = s[nt][0], p1 = s[nt][1], p2 = s[nt][2], p3 = s[nt][3];
            unsigned h0 = f2tf(p0), h1 = f2tf(p1), h2 = f2tf(p2), h3 = f2tf(p3);
            int c = nt*8 + t4*2;
            *(float2*)(Ph + lr0*68 + c) = make_float2(__uint_as_float(h0), __uint_as_float(h1));
            *(float2*)(Ph + lr1*68 + c) = make_float2(__uint_as_float(h2), __uint_as_float(h3));
            *(float2*)(Pl + lr0*68 + c) = make_float2(
                __uint_as_float(f2tf(p0 - __uint_as_float(h0))),
                __uint_as_float(f2tf(p1 - __uint_as_float(h1))));
            *(float2*)(Pl + lr1*68 + c) = make_float2(
                __uint_as_float(f2tf(p2 - __uint_as_float(h2))),
                __uint_as_float(f2tf(p3 - __uint_as_float(h3))));
            o[nt][0] *= al0; o[nt][1] *= al0;
            o[nt][2] *= al1; o[nt][3] *= al1;
        }
        __syncthreads();

        // PV split-tf32 MMA: o[nt] += P[128x64] * V[64x64]
#pragma unroll
        for (int kb = 0; kb < 8; kb++) {
            int arow = lr0*68 + kb*8 + t4;
            unsigned ah[4], al2[4];
            ah[0] = __float_as_uint(Ph[arow]);
            ah[1] = __float_as_uint(Ph[arow + 8*68]);
            ah[2] = __float_as_uint(Ph[arow + 4]);
            ah[3] = __float_as_uint(Ph[arow + 8*68 + 4]);
            al2[0] = __float_as_uint(Pl[arow]);
            al2[1] = __float_as_uint(Pl[arow + 8*68]);
            al2[2] = __float_as_uint(Pl[arow + 4]);
            al2[3] = __float_as_uint(Pl[arow + 8*68 + 4]);
            int krow = (kb*8 + t4)*72;
#pragma unroll
            for (int nt = 0; nt < 8; nt++) {
                int bcol = nt*8 + gp;
                unsigned bh0 = __float_as_uint(Vh[krow + bcol]);
                unsigned bh1 = __float_as_uint(Vh[krow + 4*72 + bcol]);
                unsigned bl0 = __float_as_uint(Vl[krow + bcol]);
                unsigned bl1 = __float_as_uint(Vl[krow + 4*72 + bcol]);
                mma_tf32(o[nt], ah, bh0, bh1);
                mma_tf32(o[nt], ah, bl0, bl1);
                mma_tf32(o[nt], al2, bh0, bh1);
            }
        }
    }
    float inv0 = 1.f / l0, inv1 = 1.f / l1;
    size_t ob0 = ((size_t)(b*S_ + qt*128 + lr0))*(H_*HD_) + h*HD_;
    size_t ob1 = ((size_t)(b*S_ + qt*128 + lr1))*(H_*HD_) + h*HD_;
#pragma unroll
    for (int nt = 0; nt < 8; nt++) {
        int c = nt*8 + t4*2;
        *(float2*)(O + ob0 + c) = make_float2(o[nt][0]*inv0, o[nt][1]*inv0);
        *(float2*)(O + ob1 + c) = make_float2(o[nt][2]*inv1, o[nt][3]*inv1);
    }
}

// ======= elementwise =======
__global__ void gatemul_kernel() {
    size_t i = (size_t)blockIdx.x * 256 + threadIdx.x;
    float4 g = ((float4*)g_gate)[i];
    float4 a = ((float4*)g_attn)[i];
    g.x = a.x / (1.f + __expf(-g.x));
    g.y = a.y / (1.f + __expf(-g.y));
    g.z = a.z / (1.f + __expf(-g.z));
    g.w = a.w / (1.f + __expf(-g.w));
    ((float4*)g_gate)[i] = g;
}
__global__ void silumul_kernel() {
    size_t i = (size_t)blockIdx.x * 256 + threadIdx.x;
    float4 a = ((float4*)g_h)[i];
    float4 b = ((float4*)g_h3)[i];
    a.x = a.x / (1.f + __expf(-a.x)) * b.x;
    a.y = a.y / (1.f + __expf(-a.y)) * b.y;
    a.z = a.z / (1.f + __expf(-a.z)) * b.z;
    a.w = a.w / (1.f + __expf(-a.w)) * b.w;
    ((float4*)g_h)[i] = a;
}

// ======= router + moe bookkeeping =======
__global__ void router_kernel(const float* __restrict__ rw) {
    int t = blockIdx.x;
    const float* x = g_xn2 + (size_t)t * D_;
    float le[8] = {0,0,0,0,0,0,0,0};
    for (int d = threadIdx.x; d < D_; d += 256) {
        float xv = x[d];
        const float4* r4 = (const float4*)(rw + (size_t)d * 8);
        float4 aa = r4[0], bb = r4[1];
        le[0] += xv*aa.x; le[1] += xv*aa.y; le[2] += xv*aa.z; le[3] += xv*aa.w;
        le[4] += xv*bb.x; le[5] += xv*bb.y; le[6] += xv*bb.z; le[7] += xv*bb.w;
    }
#pragma unroll
    for (int e = 0; e < 8; e++)
        for (int o = 16; o > 0; o >>= 1)
            le[e] += __shfl_xor_sync(0xffffffffu, le[e], o);
    __shared__ float smr[8][8];
    if ((threadIdx.x & 31) == 0)
#pragma unroll
        for (int e = 0; e < 8; e++) smr[threadIdx.x >> 5][e] = le[e];
    __syncthreads();
    if (threadIdx.x == 0) {
        float lg[8];
#pragma unroll
        for (int e = 0; e < 8; e++) {
            float s = 0.f;
            for (int w2 = 0; w2 < 8; w2++) s += smr[w2][e];
            lg[e] = s;
        }
        float mx = lg[0];
        for (int e = 1; e < 8; e++) mx = fmaxf(mx, lg[e]);
        float p[8], s = 0.f;
        for (int e = 0; e < 8; e++) { p[e] = expf(lg[e] - mx); s += p[e]; }
        float invs = 1.f / s;
        for (int e = 0; e < 8; e++) { p[e] *= invs; atomicAdd(&g_probsum[e], p[e]); }
        int i0 = 0;
        for (int e = 1; e < 8; e++) if (p[e] > p[i0]) i0 = e;
        int i1 = (i0 == 0) ? 1 : 0;
        for (int e = 0; e < 8; e++) if (e != i0 && p[e] > p[i1]) i1 = e;
        float tv0 = p[i0], tv1 = p[i1], s2 = tv0 + tv1;
        g_topi[t*2] = i0; g_topi[t*2+1] = i1;
        g_topv[t*2] = tv0/s2; g_topv[t*2+1] = tv1/s2;
        atomicAdd(&g_counts[i0], 1);
        atomicAdd(&g_counts[i1], 1);
    }
}
__global__ void zero_kernel() {
    int t = threadIdx.x;
    if (t < E_) { g_counts[t] = 0; g_cursor[t] = 0; g_probsum[t] = 0.f; }
}
__global__ void offsets_aux_kernel(float* __restrict__ aux_out) {
    if (threadIdx.x == 0) {
        int o = 0;
        for (int e = 0; e < E_; e++) { g_off[e] = o; o += g_counts[e]; }
        g_off[E_] = o;
        float aux = 0.f;
        for (int e = 0; e < E_; e++)
            aux += ((float)g_counts[e] / (NTOK*2.0f)) * (g_probsum[e] / (float)NTOK);
        aux_out[0] = 0.01f * (float)E_ * aux;
    }
}
__global__ void scatter_kernel() {
    int t = blockIdx.x * 256 + threadIdx.x;
    if (t >= NTOK) return;
#pragma unroll
    for (int k2 = 0; k2 < 2; k2++) {
        int e = g_topi[t*2+k2];
        int pos = g_off[e] + atomicAdd(&g_cursor[e], 1);
        g_permTok[pos] = t;
        g_permW[pos] = g_topv[t*2+k2];
        g_tokSlot[t*2+k2] = pos;
    }
}
__global__ void finaladd_kernel(float* __restrict__ out) {
    size_t i = (size_t)blockIdx.x * 256 + threadIdx.x;
    int t = (int)(i >> 10);
    int d = (int)(i & 1023);
    int s0 = g_tokSlot[t*2], s1 = g_tokSlot[t*2+1];
    out[i] = g_x1[i] + g_tmp[(size_t)s0*D_ + d] + g_tmp[(size_t)s1*D_ + d];
}

// ======= host launcher =======
extern "C" void kernel_launch(void* const* d_in, const int* in_sizes, int n_in,
                              void* d_out, int out_size) {
    const float* x        = (const float*)d_in[0];
    const float* attn_nw  = (const float*)d_in[1];
    const float* ffn_nw   = (const float*)d_in[2];
    const float* q_nw     = (const float*)d_in[3];
    const float* k_nw     = (const float*)d_in[4];
    const float* wq       = (const float*)d_in[5];
    const float* wk       = (const float*)d_in[6];
    const float* wv       = (const float*)d_in[7];
    const float* wo       = (const float*)d_in[8];
    const float* wg       = (const float*)d_in[9];
    const float* router_w = (const float*)d_in[10];
    const float* w1       = (const float*)d_in[11];
    const float* w3       = (const float*)d_in[12];
    const float* w2       = (const float*)d_in[13];
    float* out = (float*)d_out;

    float *p_xn, *p_q, *p_k, *p_v, *p_gate, *p_x1, *p_xn2, *p_attn;
    cudaGetSymbolAddress((void**)&p_xn, g_xn);
    cudaGetSymbolAddress((void**)&p_q, g_q);
    cudaGetSymbolAddress((void**)&p_k, g_k);
    cudaGetSymbolAddress((void**)&p_v, g_v);
    cudaGetSymbolAddress((void**)&p_gate, g_gate);
    cudaGetSymbolAddress((void**)&p_attn, g_attn);
    cudaGetSymbolAddress((void**)&p_x1, g_x1);
    cudaGetSymbolAddress((void**)&p_xn2, g_xn2);

    cudaFuncSetAttribute(proj_gemm, cudaFuncAttributeMaxDynamicSharedMemorySize, SMEM_GEMM_S);
    cudaFuncSetAttribute(gemm_plain<1,true>, cudaFuncAttributeMaxDynamicSharedMemorySize, SMEM_GEMM_S);
    cudaFuncSetAttribute(moe13_gemm, cudaFuncAttributeMaxDynamicSharedMemorySize, SMEM_GEMM);
    cudaFuncSetAttribute(moe2_gemm, cudaFuncAttributeMaxDynamicSharedMemorySize, SMEM_GEMM);
    cudaFuncSetAttribute(attn_tc2, cudaFuncAttributeMaxDynamicSharedMemorySize, SMEM_ATTN3);

    rmsnorm_kernel<<<NTOK, 256>>>(x, attn_nw, p_xn, 1e-6f);
    proj_gemm<<<dim3(20,32), 256, SMEM_GEMM_S>>>(wq, wk, wv, wg);
    qkrope_kernel<<<(NTOK*H_*32)/256, 256>>>(p_q, q_nw, H_);
    qkrope_kernel<<<(NTOK*KH_*32)/256, 256>>>(p_k, k_nw, KH_);
    attn_tc2<<<dim3(S_/128, H_, B_), 256, SMEM_ATTN3>>>(p_q, p_k, p_v, p_attn);
    gatemul_kernel<<<(NTOK*1024/4)/256, 256>>>();
    gemm_plain<1,true><<<dim3(8,32), 256, SMEM_GEMM_S>>>(p_gate, wo, p_x1, x, 1024, 1024, NTOK);
    rmsnorm_kernel<<<NTOK, 256>>>(p_x1, ffn_nw, p_xn2, 1e-6f);
    zero_kernel<<<1, 32>>>();
    router_kernel<<<NTOK, 256>>>(router_w);
    offsets_aux_kernel<<<1, 32>>>(out + (size_t)NTOK*D_);
    scatter_kernel<<<NTOK/256, 256>>>();
    moe13_gemm<<<dim3(FF_/128, 32, 16), 256, SMEM_GEMM>>>(w1, w3);
    silumul_kernel<<<((size_t)NSLOT*FF_/4)/256, 256>>>();
    moe2_gemm<<<dim3(D_/128, 32, 8), 256, SMEM_GEMM>>>(w2);
    finaladd_kernel<<<(NTOK*1024)/256, 256>>>(out);
}